// round 1
// baseline (speedup 1.0000x reference)
#include <cuda_runtime.h>
#include <math.h>

#define L_TOK 3840
#define DIM   1536
#define NH    12
#define HD    128
#define FRAME 480
#define NPAIR 64

// ---------------- device scratch (no allocs allowed) ----------------
__device__ float g_q[L_TOK * DIM];
__device__ float g_k[L_TOK * DIM];
__device__ float g_v[L_TOK * DIM];
__device__ float g_attn[L_TOK * DIM];
__device__ float g_cos[L_TOK * NPAIR];
__device__ float g_sin[L_TOK * NPAIR];

// ---------------- angle table ----------------
__global__ void angles_kernel(const float* __restrict__ ff,
                              const float* __restrict__ fh,
                              const float* __restrict__ fw) {
    int idx = blockIdx.x * blockDim.x + threadIdx.x;
    if (idx >= L_TOK * NPAIR) return;
    int l = idx / NPAIR, j = idx % NPAIR;
    int f = l / FRAME, r = l % FRAME;
    int h = r / 30, w = r % 30;
    float a;
    if (j < 22)      a = ff[f * 22 + j];
    else if (j < 43) a = fh[h * 21 + (j - 22)];
    else             a = fw[w * 21 + (j - 43)];
    g_cos[idx] = cosf(a);
    g_sin[idx] = sinf(a);
}

// ---------------- SGEMM: C[M,N] = A[M,K] @ B[K,N] + bias ----------------
// 128x128 block, BK=8, 256 threads, 8x8 microtile, register prefetch.
__global__ __launch_bounds__(256) void sgemm_bias(const float* __restrict__ A,
                                                  const float* __restrict__ B,
                                                  const float* __restrict__ bias,
                                                  float* __restrict__ C,
                                                  int M, int N, int K) {
    __shared__ float As[8][132];   // transposed A tile, padded
    __shared__ float Bs[8][128];

    int tid = threadIdx.x;
    int bm = blockIdx.y, bn = blockIdx.x;

    int a_row = tid >> 1;           // 0..127
    int a_col = (tid & 1) * 4;      // 0 or 4
    int b_row = tid >> 5;           // 0..7
    int b_col = (tid & 31) * 4;     // 0..124
    int ty = tid >> 4;              // 0..15
    int tx = tid & 15;              // 0..15

    const float* Ap = A + (size_t)(bm * 128 + a_row) * K + a_col;
    const float* Bp = B + (size_t)b_row * N + (size_t)bn * 128 + b_col;

    float acc[8][8];
#pragma unroll
    for (int i = 0; i < 8; i++)
#pragma unroll
        for (int j = 0; j < 8; j++) acc[i][j] = 0.f;

    int nk = K >> 3;
    float4 av = *(const float4*)Ap;
    float4 bv = *(const float4*)Bp;

    for (int kt = 0; kt < nk; kt++) {
        As[a_col + 0][a_row] = av.x;
        As[a_col + 1][a_row] = av.y;
        As[a_col + 2][a_row] = av.z;
        As[a_col + 3][a_row] = av.w;
        *(float4*)&Bs[b_row][b_col] = bv;
        __syncthreads();

        if (kt + 1 < nk) {
            av = *(const float4*)(Ap + (size_t)(kt + 1) * 8);
            bv = *(const float4*)(Bp + (size_t)(kt + 1) * 8 * N);
        }

#pragma unroll
        for (int k = 0; k < 8; k++) {
            float4 a0 = *(const float4*)&As[k][ty * 8];
            float4 a1 = *(const float4*)&As[k][ty * 8 + 4];
            float4 b0 = *(const float4*)&Bs[k][tx * 4];
            float4 b1 = *(const float4*)&Bs[k][64 + tx * 4];
            float ar[8] = {a0.x, a0.y, a0.z, a0.w, a1.x, a1.y, a1.z, a1.w};
            float br[8] = {b0.x, b0.y, b0.z, b0.w, b1.x, b1.y, b1.z, b1.w};
#pragma unroll
            for (int i = 0; i < 8; i++)
#pragma unroll
                for (int j = 0; j < 8; j++) acc[i][j] += ar[i] * br[j];
        }
        __syncthreads();
    }

    int crow = bm * 128 + ty * 8;
    int c0 = bn * 128 + tx * 4;
    int c1 = bn * 128 + 64 + tx * 4;
    float4 bi0 = *(const float4*)&bias[c0];
    float4 bi1 = *(const float4*)&bias[c1];
#pragma unroll
    for (int i = 0; i < 8; i++) {
        float4 o0 = {acc[i][0] + bi0.x, acc[i][1] + bi0.y,
                     acc[i][2] + bi0.z, acc[i][3] + bi0.w};
        float4 o1 = {acc[i][4] + bi1.x, acc[i][5] + bi1.y,
                     acc[i][6] + bi1.z, acc[i][7] + bi1.w};
        *(float4*)&C[(size_t)(crow + i) * N + c0] = o0;
        *(float4*)&C[(size_t)(crow + i) * N + c1] = o1;
    }
}

// ---------------- RMSNorm (over DIM) + RoPE, in place ----------------
__global__ __launch_bounds__(256) void rmsnorm_rope(float* __restrict__ x,
                                                    const float* __restrict__ g) {
    int row = blockIdx.x;
    float* xp = x + (size_t)row * DIM;
    int tid = threadIdx.x;

    float ss = 0.f;
    for (int i = tid; i < DIM; i += 256) {
        float v = xp[i];
        ss += v * v;
    }
    __shared__ float red[8];
#pragma unroll
    for (int m = 16; m; m >>= 1) ss += __shfl_xor_sync(0xffffffffu, ss, m);
    if ((tid & 31) == 0) red[tid >> 5] = ss;
    __syncthreads();
    if (tid < 8) {
        float v = red[tid];
#pragma unroll
        for (int m = 4; m; m >>= 1) v += __shfl_xor_sync(0xffu, v, m);
        if (tid == 0) red[0] = rsqrtf(v * (1.0f / DIM) + 1e-6f);
    }
    __syncthreads();
    float scale = red[0];

    for (int p = tid; p < NH * NPAIR; p += 256) {
        int head = p >> 6, j = p & 63;
        int i0 = head * HD + 2 * j;
        float2 v = *(float2*)&xp[i0];
        float2 gv = *(const float2*)&g[i0];
        float xr = v.x * scale * gv.x;
        float xi = v.y * scale * gv.y;
        float c = g_cos[row * NPAIR + j];
        float s = g_sin[row * NPAIR + j];
        float2 o = {xr * c - xi * s, xr * s + xi * c};
        *(float2*)&xp[i0] = o;
    }
}

// ---------------- Flash attention (frame-causal) ----------------
// grid (60, 12): x = q-block (reversed for load balance), y = head.
// 256 threads: ty=tid/16 owns q-rows 4ty..4ty+3; tx=tid%16 owns
// k-cols 4tx..4tx+3 (S stage) and dims {4tx..4tx+3, 64+4tx..64+4tx+3} (PV).
#define ATT_SMEM ((64 * 132 + 128 * 68 + 64 * 132 + 64 * 65) * 4)

__global__ __launch_bounds__(256, 1) void attention_kernel() {
    extern __shared__ float sm[];
    float* Qs = sm;                   // [64][132]
    float* Kt = Qs + 64 * 132;        // [128][68]  (transposed: [d][col])
    float* Vs = Kt + 128 * 68;        // [64][132]
    float* Pt = Vs + 64 * 132;        // [64][65]   (transposed: [key][row])

    int qb = 59 - blockIdx.x;         // heaviest blocks launch first
    int h = blockIdx.y;
    int tid = threadIdx.x;
    int ty = tid >> 4, tx = tid & 15;
    int q0 = qb * 64;

    // Load Q tile (coalesced)
    for (int i = tid; i < 64 * 32; i += 256) {
        int r = i >> 5, d4 = i & 31;
        float4 v = *(const float4*)&g_q[(size_t)(q0 + r) * DIM + h * HD + d4 * 4];
        *(float4*)&Qs[r * 132 + d4 * 4] = v;
    }

    float m_row[4], l_row[4], O[4][8];
    int fq[4];
#pragma unroll
    for (int i = 0; i < 4; i++) {
        m_row[i] = -1e30f;
        l_row[i] = 0.f;
        fq[i] = (q0 + 4 * ty + i) / FRAME;
#pragma unroll
        for (int d = 0; d < 8; d++) O[i][d] = 0.f;
    }
    int fqmax = (q0 + 63) / FRAME;
    int kv_end = (fqmax + 1) * FRAME;
    int ntile = (kv_end + 63) >> 6;
    const float scale = 0.08838834764831845f;  // 1/sqrt(128)

    int kquarter = tid & 3;
    int krow = tid >> 2;

    for (int t = 0; t < ntile; t++) {
        int k0 = t * 64;
        // K tile, transposed into Kt[d][col]
#pragma unroll
        for (int it = 0; it < 8; it++) {
            int d4 = kquarter * 8 + it;
            float4 v = *(const float4*)&g_k[(size_t)(k0 + krow) * DIM + h * HD + d4 * 4];
            Kt[(d4 * 4 + 0) * 68 + krow] = v.x;
            Kt[(d4 * 4 + 1) * 68 + krow] = v.y;
            Kt[(d4 * 4 + 2) * 68 + krow] = v.z;
            Kt[(d4 * 4 + 3) * 68 + krow] = v.w;
        }
        // V tile (natural layout)
        for (int i = tid; i < 64 * 32; i += 256) {
            int r = i >> 5, d4 = i & 31;
            float4 v = *(const float4*)&g_v[(size_t)(k0 + r) * DIM + h * HD + d4 * 4];
            *(float4*)&Vs[r * 132 + d4 * 4] = v;
        }
        __syncthreads();

        // S = Q @ K^T for 4x4 microtile
        float s[4][4];
#pragma unroll
        for (int i = 0; i < 4; i++)
#pragma unroll
            for (int j = 0; j < 4; j++) s[i][j] = 0.f;

#pragma unroll 4
        for (int d = 0; d < 128; d += 4) {
            float qv[4][4], kv[4][4];
#pragma unroll
            for (int i = 0; i < 4; i++) {
                float4 q = *(const float4*)&Qs[(4 * ty + i) * 132 + d];
                qv[i][0] = q.x; qv[i][1] = q.y; qv[i][2] = q.z; qv[i][3] = q.w;
            }
#pragma unroll
            for (int dd = 0; dd < 4; dd++) {
                float4 k = *(const float4*)&Kt[(d + dd) * 68 + 4 * tx];
                kv[dd][0] = k.x; kv[dd][1] = k.y; kv[dd][2] = k.z; kv[dd][3] = k.w;
            }
#pragma unroll
            for (int dd = 0; dd < 4; dd++)
#pragma unroll
                for (int i = 0; i < 4; i++)
#pragma unroll
                    for (int j = 0; j < 4; j++)
                        s[i][j] += qv[i][dd] * kv[dd][j];
        }

        // mask + online softmax per row, write P (transposed)
#pragma unroll
        for (int i = 0; i < 4; i++) {
            float sv[4];
#pragma unroll
            for (int j = 0; j < 4; j++) {
                int kg = k0 + 4 * tx + j;
                sv[j] = ((kg / FRAME) <= fq[i]) ? s[i][j] * scale : -1e30f;
            }
            float m = fmaxf(fmaxf(sv[0], sv[1]), fmaxf(sv[2], sv[3]));
            m = fmaxf(m, __shfl_xor_sync(0xffffffffu, m, 1));
            m = fmaxf(m, __shfl_xor_sync(0xffffffffu, m, 2));
            m = fmaxf(m, __shfl_xor_sync(0xffffffffu, m, 4));
            m = fmaxf(m, __shfl_xor_sync(0xffffffffu, m, 8));
            float mnew = fmaxf(m_row[i], m);
            float alpha = __expf(m_row[i] - mnew);
            float p0 = __expf(sv[0] - mnew);
            float p1 = __expf(sv[1] - mnew);
            float p2 = __expf(sv[2] - mnew);
            float p3 = __expf(sv[3] - mnew);
            float ps = p0 + p1 + p2 + p3;
            ps += __shfl_xor_sync(0xffffffffu, ps, 1);
            ps += __shfl_xor_sync(0xffffffffu, ps, 2);
            ps += __shfl_xor_sync(0xffffffffu, ps, 4);
            ps += __shfl_xor_sync(0xffffffffu, ps, 8);
            l_row[i] = l_row[i] * alpha + ps;
            m_row[i] = mnew;
#pragma unroll
            for (int d = 0; d < 8; d++) O[i][d] *= alpha;
            Pt[(4 * tx + 0) * 65 + 4 * ty + i] = p0;
            Pt[(4 * tx + 1) * 65 + 4 * ty + i] = p1;
            Pt[(4 * tx + 2) * 65 + 4 * ty + i] = p2;
            Pt[(4 * tx + 3) * 65 + 4 * ty + i] = p3;
        }
        __syncthreads();

        // O += P @ V
#pragma unroll 4
        for (int kk = 0; kk < 64; kk++) {
            float pf0 = Pt[kk * 65 + 4 * ty + 0];
            float pf1 = Pt[kk * 65 + 4 * ty + 1];
            float pf2 = Pt[kk * 65 + 4 * ty + 2];
            float pf3 = Pt[kk * 65 + 4 * ty + 3];
            float4 v0 = *(const float4*)&Vs[kk * 132 + 4 * tx];
            float4 v1 = *(const float4*)&Vs[kk * 132 + 64 + 4 * tx];
            float vv[8] = {v0.x, v0.y, v0.z, v0.w, v1.x, v1.y, v1.z, v1.w};
            float pf[4] = {pf0, pf1, pf2, pf3};
#pragma unroll
            for (int i = 0; i < 4; i++)
#pragma unroll
                for (int d = 0; d < 8; d++) O[i][d] += pf[i] * vv[d];
        }
        __syncthreads();
    }

    // epilogue: normalize, write
#pragma unroll
    for (int i = 0; i < 4; i++) {
        float inv = 1.0f / l_row[i];
        int row = q0 + 4 * ty + i;
        float4 o0 = {O[i][0] * inv, O[i][1] * inv, O[i][2] * inv, O[i][3] * inv};
        float4 o1 = {O[i][4] * inv, O[i][5] * inv, O[i][6] * inv, O[i][7] * inv};
        *(float4*)&g_attn[(size_t)row * DIM + h * HD + 4 * tx] = o0;
        *(float4*)&g_attn[(size_t)row * DIM + h * HD + 64 + 4 * tx] = o1;
    }
}

// ---------------- launch ----------------
extern "C" void kernel_launch(void* const* d_in, const int* in_sizes, int n_in,
                              void* d_out, int out_size) {
    const float* x  = (const float*)d_in[0];
    const float* Wq = (const float*)d_in[1];
    const float* bq = (const float*)d_in[2];
    const float* Wk = (const float*)d_in[3];
    const float* bk = (const float*)d_in[4];
    const float* Wv = (const float*)d_in[5];
    const float* bv = (const float*)d_in[6];
    const float* Wo = (const float*)d_in[7];
    const float* bo = (const float*)d_in[8];
    const float* gq = (const float*)d_in[9];
    const float* gk = (const float*)d_in[10];
    const float* ff = (const float*)d_in[11];
    const float* fh = (const float*)d_in[12];
    const float* fw = (const float*)d_in[13];
    float* out = (float*)d_out;

    float *qp, *kp, *vp, *ap;
    cudaGetSymbolAddress((void**)&qp, g_q);
    cudaGetSymbolAddress((void**)&kp, g_k);
    cudaGetSymbolAddress((void**)&vp, g_v);
    cudaGetSymbolAddress((void**)&ap, g_attn);

    cudaFuncSetAttribute(attention_kernel,
                         cudaFuncAttributeMaxDynamicSharedMemorySize, ATT_SMEM);

    angles_kernel<<<(L_TOK * NPAIR + 255) / 256, 256>>>(ff, fh, fw);

    dim3 ggrid(DIM / 128, L_TOK / 128);
    sgemm_bias<<<ggrid, 256>>>(x, Wq, bq, qp, L_TOK, DIM, DIM);
    sgemm_bias<<<ggrid, 256>>>(x, Wk, bk, kp, L_TOK, DIM, DIM);
    sgemm_bias<<<ggrid, 256>>>(x, Wv, bv, vp, L_TOK, DIM, DIM);

    rmsnorm_rope<<<L_TOK, 256>>>(qp, gq);
    rmsnorm_rope<<<L_TOK, 256>>>(kp, gk);

    attention_kernel<<<dim3(60, NH), 256, ATT_SMEM>>>();

    sgemm_bias<<<ggrid, 256>>>(ap, Wo, bo, out, L_TOK, DIM, DIM);
}

// round 3
// speedup vs baseline: 1.3775x; 1.3775x over previous
#include <cuda_runtime.h>
#include <cuda_bf16.h>
#include <math.h>
#include <stdint.h>

#define L_TOK 3840
#define DIM   1536
#define NH    12
#define HD    128
#define FRAME 480
#define NPAIR 64

// ---------------- device scratch (no allocs allowed) ----------------
__device__ float g_q[L_TOK * DIM];
__device__ float g_k[L_TOK * DIM];
__device__ float g_v[L_TOK * DIM];
__device__ float g_attn[L_TOK * DIM];
__device__ float g_cos[L_TOK * NPAIR];
__device__ float g_sin[L_TOK * NPAIR];
__device__ __nv_bfloat16 g_ah[L_TOK * DIM];   // A hi (x, later attn out)
__device__ __nv_bfloat16 g_al[L_TOK * DIM];   // A lo
__device__ __nv_bfloat16 g_bh[DIM * DIM];     // W^T hi  [N][K]
__device__ __nv_bfloat16 g_bl[DIM * DIM];     // W^T lo

// =================== sm_80-era PTX helpers (valid on plain sm_103) ==========
__device__ __forceinline__ uint32_t smem_u32(const void* p) {
    uint32_t a;
    asm("{ .reg .u64 t; cvta.to.shared.u64 t, %1; cvt.u32.u64 %0, t; }" : "=r"(a) : "l"(p));
    return a;
}
#define CP_ASYNC16(dst, src) \
    asm volatile("cp.async.cg.shared.global [%0], [%1], 16;" :: "r"(dst), "l"(src))
#define CP_COMMIT() asm volatile("cp.async.commit_group;" ::: "memory")
#define CP_WAIT1()  asm volatile("cp.async.wait_group 1;" ::: "memory")
#define CP_WAIT0()  asm volatile("cp.async.wait_group 0;" ::: "memory")

__device__ __forceinline__ void ldsm4(uint32_t* r, uint32_t addr) {
    asm volatile("ldmatrix.sync.aligned.m8n8.x4.shared.b16 {%0,%1,%2,%3}, [%4];"
                 : "=r"(r[0]), "=r"(r[1]), "=r"(r[2]), "=r"(r[3]) : "r"(addr));
}
__device__ __forceinline__ void mma16816(float* c, const uint32_t* a, const uint32_t* b) {
    asm volatile("mma.sync.aligned.m16n8k16.row.col.f32.bf16.bf16.f32 "
                 "{%0,%1,%2,%3}, {%4,%5,%6,%7}, {%8,%9}, {%0,%1,%2,%3};"
                 : "+f"(c[0]), "+f"(c[1]), "+f"(c[2]), "+f"(c[3])
                 : "r"(a[0]), "r"(a[1]), "r"(a[2]), "r"(a[3]), "r"(b[0]), "r"(b[1]));
}
#define SWZ128(off) ((off) ^ (((off) >> 3) & 0x70))

// ---------------- angle table ----------------
__global__ void angles_kernel(const float* __restrict__ ff,
                              const float* __restrict__ fh,
                              const float* __restrict__ fw) {
    int idx = blockIdx.x * blockDim.x + threadIdx.x;
    if (idx >= L_TOK * NPAIR) return;
    int l = idx / NPAIR, j = idx % NPAIR;
    int f = l / FRAME, r = l % FRAME;
    int h = r / 30, w = r % 30;
    float a;
    if (j < 22)      a = ff[f * 22 + j];
    else if (j < 43) a = fh[h * 21 + (j - 22)];
    else             a = fw[w * 21 + (j - 43)];
    g_cos[idx] = cosf(a);
    g_sin[idx] = sinf(a);
}

// ---------------- split fp32 -> bf16 hi/lo ----------------
__global__ __launch_bounds__(256) void split_kernel(const float* __restrict__ x,
                                                    __nv_bfloat16* __restrict__ hi,
                                                    __nv_bfloat16* __restrict__ lo, int n) {
    int i = blockIdx.x * blockDim.x + threadIdx.x;
    if (i * 4 >= n) return;
    float4 v = *(const float4*)&x[i * 4];
    __nv_bfloat16 h0 = __float2bfloat16(v.x), h1 = __float2bfloat16(v.y);
    __nv_bfloat16 h2 = __float2bfloat16(v.z), h3 = __float2bfloat16(v.w);
    __nv_bfloat16 l0 = __float2bfloat16(v.x - __bfloat162float(h0));
    __nv_bfloat16 l1 = __float2bfloat16(v.y - __bfloat162float(h1));
    __nv_bfloat16 l2 = __float2bfloat16(v.z - __bfloat162float(h2));
    __nv_bfloat16 l3 = __float2bfloat16(v.w - __bfloat162float(h3));
    __nv_bfloat162* ph = (__nv_bfloat162*)&hi[i * 4];
    __nv_bfloat162* pl = (__nv_bfloat162*)&lo[i * 4];
    ph[0] = {h0, h1}; ph[1] = {h2, h3};
    pl[0] = {l0, l1}; pl[1] = {l2, l3};
}

// ---------------- transpose W [K,N] -> Wt [N,K] with hi/lo split ----------------
__global__ __launch_bounds__(256) void transpose_split_kernel(const float* __restrict__ W,
                                                              __nv_bfloat16* __restrict__ Th,
                                                              __nv_bfloat16* __restrict__ Tl) {
    __shared__ float t[32][33];
    int tx = threadIdx.x, ty = threadIdx.y;  // 32 x 8
    int x0 = blockIdx.x * 32, y0 = blockIdx.y * 32;
#pragma unroll
    for (int i = 0; i < 32; i += 8)
        t[ty + i][tx] = W[(size_t)(y0 + ty + i) * DIM + x0 + tx];
    __syncthreads();
#pragma unroll
    for (int i = 0; i < 32; i += 8) {
        float v = t[tx][ty + i];
        __nv_bfloat16 h = __float2bfloat16(v);
        __nv_bfloat16 l = __float2bfloat16(v - __bfloat162float(h));
        size_t o = (size_t)(x0 + ty + i) * DIM + y0 + tx;
        Th[o] = h;
        Tl[o] = l;
    }
}

// ---------------- HMMA split-bf16 GEMM ----------------
// C[3840,1536] = A @ W + bias;  A = Ah+Al [M,K] bf16, B = W^T = Bh+Bl [N,K] bf16
// C ≈ AhBh + AhBl + AlBh (fp32 accum).
// CTA 128x128, BK=64, double-buffered cp.async, 8 warps (4m x 2n), warp 32x64.
#define GK       64
#define TILE_B   16384                       // 128 rows x 128 bytes
#define BUF_B    (4 * TILE_B)                // Ah, Al, Bh, Bl
#define GSMEM    (1024 + 2 * BUF_B)

__global__ __launch_bounds__(256, 1) void gemm_hmma(const __nv_bfloat16* __restrict__ Ah,
                                                    const __nv_bfloat16* __restrict__ Al,
                                                    const __nv_bfloat16* __restrict__ Bh,
                                                    const __nv_bfloat16* __restrict__ Bl,
                                                    const float* __restrict__ bias,
                                                    float* __restrict__ C) {
    extern __shared__ char dsm[];
    uint32_t raw = smem_u32(dsm);
    uint32_t sbase = (raw + 1023u) & ~1023u;

    int tid = threadIdx.x;
    int wid = tid >> 5, lane = tid & 31;
    int m0 = blockIdx.y * 128;
    int n0 = blockIdx.x * 128;

    const __nv_bfloat16* srcs[4] = {Ah, Al, Bh, Bl};
    const int rbase[4] = {m0, m0, n0, n0};

    // ---- async tile loader: chunk c into buffer buf ----
    auto load_chunk = [&](int c, int buf) {
        uint32_t dst0 = sbase + (uint32_t)buf * BUF_B;
#pragma unroll
        for (int it = 0; it < 16; it++) {
            int idx = it * 256 + tid;
            int tile = idx >> 10;
            int rem = idx & 1023;
            int r = rem >> 3, g = rem & 7;
            const __nv_bfloat16* src = srcs[tile] + (size_t)(rbase[tile] + r) * DIM + c * GK + g * 8;
            uint32_t off = (uint32_t)(r * 128 + g * 16);
            CP_ASYNC16(dst0 + (uint32_t)tile * TILE_B + SWZ128(off), src);
        }
    };

    float Creg[2][8][4];
#pragma unroll
    for (int mt = 0; mt < 2; mt++)
#pragma unroll
        for (int nf = 0; nf < 8; nf++)
#pragma unroll
            for (int j = 0; j < 4; j++) Creg[mt][nf][j] = 0.f;

    int m_base = (wid & 3) * 32;
    int n_base = (wid >> 2) * 64;
    // lane-derived ldmatrix row/granule components
    int a_r = m_base + (lane & 7) + ((lane >> 3) & 1) * 8;   // + mt*16
    int a_g = (lane >> 4);                                   // + 2ks
    int b_r = n_base + ((lane >> 4) & 1) * 8 + (lane & 7);   // + nf2*16
    int b_g = (lane >> 3) & 1;                               // + 2ks

    const int NCH = DIM / GK;  // 24
    load_chunk(0, 0); CP_COMMIT();
    load_chunk(1, 1); CP_COMMIT();

    for (int c = 0; c < NCH; c++) {
        if (c == NCH - 1) CP_WAIT0(); else CP_WAIT1();
        __syncthreads();

        int buf = c & 1;
        uint32_t sb = sbase + (uint32_t)buf * BUF_B;
        uint32_t sAh = sb, sAl = sb + TILE_B, sBh = sb + 2 * TILE_B, sBl = sb + 3 * TILE_B;

#pragma unroll
        for (int ks = 0; ks < 4; ks++) {
            uint32_t ah[2][4], al[2][4], bh[16], bl[16];
#pragma unroll
            for (int mt = 0; mt < 2; mt++) {
                uint32_t off = SWZ128((uint32_t)((a_r + mt * 16) * 128 + (a_g + 2 * ks) * 16));
                ldsm4(ah[mt], sAh + off);
                ldsm4(al[mt], sAl + off);
            }
#pragma unroll
            for (int nf2 = 0; nf2 < 4; nf2++) {
                uint32_t off = SWZ128((uint32_t)((b_r + nf2 * 16) * 128 + (b_g + 2 * ks) * 16));
                ldsm4(&bh[nf2 * 4], sBh + off);
                ldsm4(&bl[nf2 * 4], sBl + off);
            }
#pragma unroll
            for (int nf = 0; nf < 8; nf++) {
                const uint32_t* bhf = &bh[nf * 2];
                const uint32_t* blf = &bl[nf * 2];
#pragma unroll
                for (int mt = 0; mt < 2; mt++) {
                    mma16816(Creg[mt][nf], ah[mt], bhf);
                    mma16816(Creg[mt][nf], ah[mt], blf);
                    mma16816(Creg[mt][nf], al[mt], bhf);
                }
            }
        }
        __syncthreads();
        if (c + 2 < NCH) { load_chunk(c + 2, buf); CP_COMMIT(); }
    }

    // epilogue
#pragma unroll
    for (int mt = 0; mt < 2; mt++) {
#pragma unroll
        for (int nf = 0; nf < 8; nf++) {
            int r0 = m0 + m_base + mt * 16 + (lane >> 2);
            int col = n0 + n_base + nf * 8 + (lane & 3) * 2;
            float2 bv = *(const float2*)&bias[col];
            float* cc = Creg[mt][nf];
            float2 o0 = {cc[0] + bv.x, cc[1] + bv.y};
            float2 o1 = {cc[2] + bv.x, cc[3] + bv.y};
            *(float2*)&C[(size_t)r0 * DIM + col] = o0;
            *(float2*)&C[(size_t)(r0 + 8) * DIM + col] = o1;
        }
    }
}

// ---------------- RMSNorm (over DIM) + RoPE, in place ----------------
__global__ __launch_bounds__(256) void rmsnorm_rope(float* __restrict__ x,
                                                    const float* __restrict__ g) {
    int row = blockIdx.x;
    float* xp = x + (size_t)row * DIM;
    int tid = threadIdx.x;

    float ss = 0.f;
    for (int i = tid; i < DIM; i += 256) {
        float v = xp[i];
        ss += v * v;
    }
    __shared__ float red[8];
#pragma unroll
    for (int m = 16; m; m >>= 1) ss += __shfl_xor_sync(0xffffffffu, ss, m);
    if ((tid & 31) == 0) red[tid >> 5] = ss;
    __syncthreads();
    if (tid < 8) {
        float v = red[tid];
#pragma unroll
        for (int m = 4; m; m >>= 1) v += __shfl_xor_sync(0xffu, v, m);
        if (tid == 0) red[0] = rsqrtf(v * (1.0f / DIM) + 1e-6f);
    }
    __syncthreads();
    float scale = red[0];

    for (int p = tid; p < NH * NPAIR; p += 256) {
        int head = p >> 6, j = p & 63;
        int i0 = head * HD + 2 * j;
        float2 v = *(float2*)&xp[i0];
        float2 gv = *(const float2*)&g[i0];
        float xr = v.x * scale * gv.x;
        float xi = v.y * scale * gv.y;
        float c = g_cos[row * NPAIR + j];
        float s = g_sin[row * NPAIR + j];
        float2 o = {xr * c - xi * s, xr * s + xi * c};
        *(float2*)&xp[i0] = o;
    }
}

// ---------------- Flash attention (frame-causal) ----------------
#define ATT_SMEM ((64 * 132 + 128 * 68 + 64 * 132 + 64 * 65) * 4)

__global__ __launch_bounds__(256, 1) void attention_kernel() {
    extern __shared__ float sm[];
    float* Qs = sm;                   // [64][132]
    float* Kt = Qs + 64 * 132;        // [128][68]  (transposed: [d][col])
    float* Vs = Kt + 128 * 68;        // [64][132]
    float* Pt = Vs + 64 * 132;        // [64][65]   (transposed: [key][row])

    int qb = 59 - blockIdx.x;
    int h = blockIdx.y;
    int tid = threadIdx.x;
    int ty = tid >> 4, tx = tid & 15;
    int q0 = qb * 64;

    for (int i = tid; i < 64 * 32; i += 256) {
        int r = i >> 5, d4 = i & 31;
        float4 v = *(const float4*)&g_q[(size_t)(q0 + r) * DIM + h * HD + d4 * 4];
        *(float4*)&Qs[r * 132 + d4 * 4] = v;
    }

    float m_row[4], l_row[4], O[4][8];
    int fq[4];
#pragma unroll
    for (int i = 0; i < 4; i++) {
        m_row[i] = -1e30f;
        l_row[i] = 0.f;
        fq[i] = (q0 + 4 * ty + i) / FRAME;
#pragma unroll
        for (int d = 0; d < 8; d++) O[i][d] = 0.f;
    }
    int fqmax = (q0 + 63) / FRAME;
    int kv_end = (fqmax + 1) * FRAME;
    int ntile = (kv_end + 63) >> 6;
    const float scale = 0.08838834764831845f;

    int kquarter = tid & 3;
    int krow = tid >> 2;

    for (int t = 0; t < ntile; t++) {
        int k0 = t * 64;
#pragma unroll
        for (int it = 0; it < 8; it++) {
            int d4 = kquarter * 8 + it;
            float4 v = *(const float4*)&g_k[(size_t)(k0 + krow) * DIM + h * HD + d4 * 4];
            Kt[(d4 * 4 + 0) * 68 + krow] = v.x;
            Kt[(d4 * 4 + 1) * 68 + krow] = v.y;
            Kt[(d4 * 4 + 2) * 68 + krow] = v.z;
            Kt[(d4 * 4 + 3) * 68 + krow] = v.w;
        }
        for (int i = tid; i < 64 * 32; i += 256) {
            int r = i >> 5, d4 = i & 31;
            float4 v = *(const float4*)&g_v[(size_t)(k0 + r) * DIM + h * HD + d4 * 4];
            *(float4*)&Vs[r * 132 + d4 * 4] = v;
        }
        __syncthreads();

        float s[4][4];
#pragma unroll
        for (int i = 0; i < 4; i++)
#pragma unroll
            for (int j = 0; j < 4; j++) s[i][j] = 0.f;

#pragma unroll 4
        for (int d = 0; d < 128; d += 4) {
            float qv[4][4], kv[4][4];
#pragma unroll
            for (int i = 0; i < 4; i++) {
                float4 q = *(const float4*)&Qs[(4 * ty + i) * 132 + d];
                qv[i][0] = q.x; qv[i][1] = q.y; qv[i][2] = q.z; qv[i][3] = q.w;
            }
#pragma unroll
            for (int dd = 0; dd < 4; dd++) {
                float4 k = *(const float4*)&Kt[(d + dd) * 68 + 4 * tx];
                kv[dd][0] = k.x; kv[dd][1] = k.y; kv[dd][2] = k.z; kv[dd][3] = k.w;
            }
#pragma unroll
            for (int dd = 0; dd < 4; dd++)
#pragma unroll
                for (int i = 0; i < 4; i++)
#pragma unroll
                    for (int j = 0; j < 4; j++)
                        s[i][j] += qv[i][dd] * kv[dd][j];
        }

#pragma unroll
        for (int i = 0; i < 4; i++) {
            float sv[4];
#pragma unroll
            for (int j = 0; j < 4; j++) {
                int kg = k0 + 4 * tx + j;
                sv[j] = ((kg / FRAME) <= fq[i]) ? s[i][j] * scale : -1e30f;
            }
            float m = fmaxf(fmaxf(sv[0], sv[1]), fmaxf(sv[2], sv[3]));
            m = fmaxf(m, __shfl_xor_sync(0xffffffffu, m, 1));
            m = fmaxf(m, __shfl_xor_sync(0xffffffffu, m, 2));
            m = fmaxf(m, __shfl_xor_sync(0xffffffffu, m, 4));
            m = fmaxf(m, __shfl_xor_sync(0xffffffffu, m, 8));
            float mnew = fmaxf(m_row[i], m);
            float alpha = __expf(m_row[i] - mnew);
            float p0 = __expf(sv[0] - mnew);
            float p1 = __expf(sv[1] - mnew);
            float p2 = __expf(sv[2] - mnew);
            float p3 = __expf(sv[3] - mnew);
            float ps = p0 + p1 + p2 + p3;
            ps += __shfl_xor_sync(0xffffffffu, ps, 1);
            ps += __shfl_xor_sync(0xffffffffu, ps, 2);
            ps += __shfl_xor_sync(0xffffffffu, ps, 4);
            ps += __shfl_xor_sync(0xffffffffu, ps, 8);
            l_row[i] = l_row[i] * alpha + ps;
            m_row[i] = mnew;
#pragma unroll
            for (int d = 0; d < 8; d++) O[i][d] *= alpha;
            Pt[(4 * tx + 0) * 65 + 4 * ty + i] = p0;
            Pt[(4 * tx + 1) * 65 + 4 * ty + i] = p1;
            Pt[(4 * tx + 2) * 65 + 4 * ty + i] = p2;
            Pt[(4 * tx + 3) * 65 + 4 * ty + i] = p3;
        }
        __syncthreads();

#pragma unroll 4
        for (int kk = 0; kk < 64; kk++) {
            float pf0 = Pt[kk * 65 + 4 * ty + 0];
            float pf1 = Pt[kk * 65 + 4 * ty + 1];
            float pf2 = Pt[kk * 65 + 4 * ty + 2];
            float pf3 = Pt[kk * 65 + 4 * ty + 3];
            float4 v0 = *(const float4*)&Vs[kk * 132 + 4 * tx];
            float4 v1 = *(const float4*)&Vs[kk * 132 + 64 + 4 * tx];
            float vv[8] = {v0.x, v0.y, v0.z, v0.w, v1.x, v1.y, v1.z, v1.w};
            float pf[4] = {pf0, pf1, pf2, pf3};
#pragma unroll
            for (int i = 0; i < 4; i++)
#pragma unroll
                for (int d = 0; d < 8; d++) O[i][d] += pf[i] * vv[d];
        }
        __syncthreads();
    }

#pragma unroll
    for (int i = 0; i < 4; i++) {
        float inv = 1.0f / l_row[i];
        int row = q0 + 4 * ty + i;
        float4 o0 = {O[i][0] * inv, O[i][1] * inv, O[i][2] * inv, O[i][3] * inv};
        float4 o1 = {O[i][4] * inv, O[i][5] * inv, O[i][6] * inv, O[i][7] * inv};
        *(float4*)&g_attn[(size_t)row * DIM + h * HD + 4 * tx] = o0;
        *(float4*)&g_attn[(size_t)row * DIM + h * HD + 64 + 4 * tx] = o1;
    }
}

// ---------------- launch ----------------
extern "C" void kernel_launch(void* const* d_in, const int* in_sizes, int n_in,
                              void* d_out, int out_size) {
    const float* x  = (const float*)d_in[0];
    const float* Wq = (const float*)d_in[1];
    const float* bq = (const float*)d_in[2];
    const float* Wk = (const float*)d_in[3];
    const float* bk = (const float*)d_in[4];
    const float* Wv = (const float*)d_in[5];
    const float* bv = (const float*)d_in[6];
    const float* Wo = (const float*)d_in[7];
    const float* bo = (const float*)d_in[8];
    const float* gq = (const float*)d_in[9];
    const float* gk = (const float*)d_in[10];
    const float* ff = (const float*)d_in[11];
    const float* fh = (const float*)d_in[12];
    const float* fw = (const float*)d_in[13];
    float* out = (float*)d_out;

    float *qp, *kp, *vp, *ap;
    __nv_bfloat16 *ah, *al, *bh, *bl;
    cudaGetSymbolAddress((void**)&qp, g_q);
    cudaGetSymbolAddress((void**)&kp, g_k);
    cudaGetSymbolAddress((void**)&vp, g_v);
    cudaGetSymbolAddress((void**)&ap, g_attn);
    cudaGetSymbolAddress((void**)&ah, g_ah);
    cudaGetSymbolAddress((void**)&al, g_al);
    cudaGetSymbolAddress((void**)&bh, g_bh);
    cudaGetSymbolAddress((void**)&bl, g_bl);

    cudaFuncSetAttribute(attention_kernel,
                         cudaFuncAttributeMaxDynamicSharedMemorySize, ATT_SMEM);
    cudaFuncSetAttribute(gemm_hmma,
                         cudaFuncAttributeMaxDynamicSharedMemorySize, GSMEM);

    angles_kernel<<<(L_TOK * NPAIR + 255) / 256, 256>>>(ff, fh, fw);

    const int NELT = L_TOK * DIM;
    split_kernel<<<(NELT / 4 + 255) / 256, 256>>>(x, ah, al, NELT);

    dim3 tgrid(DIM / 32, DIM / 32), tblk(32, 8);
    dim3 ggrid(DIM / 128, L_TOK / 128);

    transpose_split_kernel<<<tgrid, tblk>>>(Wq, bh, bl);
    gemm_hmma<<<ggrid, 256, GSMEM>>>(ah, al, bh, bl, bq, qp);

    transpose_split_kernel<<<tgrid, tblk>>>(Wk, bh, bl);
    gemm_hmma<<<ggrid, 256, GSMEM>>>(ah, al, bh, bl, bk, kp);

    transpose_split_kernel<<<tgrid, tblk>>>(Wv, bh, bl);
    gemm_hmma<<<ggrid, 256, GSMEM>>>(ah, al, bh, bl, bv, vp);

    rmsnorm_rope<<<L_TOK, 256>>>(qp, gq);
    rmsnorm_rope<<<L_TOK, 256>>>(kp, gk);

    attention_kernel<<<dim3(60, NH), 256, ATT_SMEM>>>();

    split_kernel<<<(NELT / 4 + 255) / 256, 256>>>(ap, ah, al, NELT);
    transpose_split_kernel<<<tgrid, tblk>>>(Wo, bh, bl);
    gemm_hmma<<<ggrid, 256, GSMEM>>>(ah, al, bh, bl, bo, out);
}

// round 4
// speedup vs baseline: 2.8212x; 2.0480x over previous
#include <cuda_runtime.h>
#include <cuda_bf16.h>
#include <math.h>
#include <stdint.h>

#define L_TOK 3840
#define DIM   1536
#define NH    12
#define HD    128
#define FRAME 480
#define NPAIR 64

// ---------------- device scratch (no allocs allowed) ----------------
__device__ float g_q[L_TOK * DIM];
__device__ float g_k[L_TOK * DIM];
__device__ float g_v[L_TOK * DIM];
__device__ float g_cos[L_TOK * NPAIR];
__device__ float g_sin[L_TOK * NPAIR];
__device__ __nv_bfloat16 g_ah[L_TOK * DIM];   // GEMM A hi (x, later attn out)
__device__ __nv_bfloat16 g_al[L_TOK * DIM];   // GEMM A lo
__device__ __nv_bfloat16 g_bh[DIM * DIM];     // W^T hi  [N][K]
__device__ __nv_bfloat16 g_bl[DIM * DIM];     // W^T lo
__device__ __nv_bfloat16 g_qh[L_TOK * DIM];
__device__ __nv_bfloat16 g_ql[L_TOK * DIM];
__device__ __nv_bfloat16 g_kh[L_TOK * DIM];
__device__ __nv_bfloat16 g_kl[L_TOK * DIM];
__device__ __nv_bfloat16 g_vh[L_TOK * DIM];
__device__ __nv_bfloat16 g_vl[L_TOK * DIM];

// =================== sm_80-era PTX helpers (valid on plain sm_103) ==========
__device__ __forceinline__ uint32_t smem_u32(const void* p) {
    uint32_t a;
    asm("{ .reg .u64 t; cvta.to.shared.u64 t, %1; cvt.u32.u64 %0, t; }" : "=r"(a) : "l"(p));
    return a;
}
#define CP_ASYNC16(dst, src) \
    asm volatile("cp.async.cg.shared.global [%0], [%1], 16;" :: "r"(dst), "l"(src))
#define CP_COMMIT() asm volatile("cp.async.commit_group;" ::: "memory")
#define CP_WAIT1()  asm volatile("cp.async.wait_group 1;" ::: "memory")
#define CP_WAIT0()  asm volatile("cp.async.wait_group 0;" ::: "memory")

__device__ __forceinline__ void ldsm4(uint32_t* r, uint32_t addr) {
    asm volatile("ldmatrix.sync.aligned.m8n8.x4.shared.b16 {%0,%1,%2,%3}, [%4];"
                 : "=r"(r[0]), "=r"(r[1]), "=r"(r[2]), "=r"(r[3]) : "r"(addr));
}
__device__ __forceinline__ void ldsm4t(uint32_t* r, uint32_t addr) {
    asm volatile("ldmatrix.sync.aligned.m8n8.x4.trans.shared.b16 {%0,%1,%2,%3}, [%4];"
                 : "=r"(r[0]), "=r"(r[1]), "=r"(r[2]), "=r"(r[3]) : "r"(addr));
}
__device__ __forceinline__ void mma16816(float* c, const uint32_t* a, const uint32_t* b) {
    asm volatile("mma.sync.aligned.m16n8k16.row.col.f32.bf16.bf16.f32 "
                 "{%0,%1,%2,%3}, {%4,%5,%6,%7}, {%8,%9}, {%0,%1,%2,%3};"
                 : "+f"(c[0]), "+f"(c[1]), "+f"(c[2]), "+f"(c[3])
                 : "r"(a[0]), "r"(a[1]), "r"(a[2]), "r"(a[3]), "r"(b[0]), "r"(b[1]));
}
#define SWZ128(off) ((off) ^ (((off) >> 3) & 0x70))

__device__ __forceinline__ uint32_t pack_bf16(float lo, float hi) {
    uint32_t r;
    asm("cvt.rn.bf16x2.f32 %0, %1, %2;" : "=r"(r) : "f"(hi), "f"(lo));
    return r;
}
// FFMA-only exp (no MUFU): exp(x) for x <= 0
__device__ __forceinline__ float exp_fast(float x) {
    x = fmaxf(x, -80.0f);
    float y = fmaf(x, 1.4426950408889634f, 12582912.0f);   // round(x*log2e) in mantissa
    float n = y - 12582912.0f;
    float f = fmaf(x, 1.4426950408889634f, -n);
    int e = __float_as_int(y) - 0x4B400000;
    float p = 0.0013333558f;
    p = fmaf(p, f, 0.0096181291f);
    p = fmaf(p, f, 0.0555041087f);
    p = fmaf(p, f, 0.2402265069f);
    p = fmaf(p, f, 0.6931471806f);
    p = fmaf(p, f, 1.0f);
    return __int_as_float(__float_as_int(p) + (e << 23));
}

// ---------------- angle table ----------------
__global__ void angles_kernel(const float* __restrict__ ff,
                              const float* __restrict__ fh,
                              const float* __restrict__ fw) {
    int idx = blockIdx.x * blockDim.x + threadIdx.x;
    if (idx >= L_TOK * NPAIR) return;
    int l = idx / NPAIR, j = idx % NPAIR;
    int f = l / FRAME, r = l % FRAME;
    int h = r / 30, w = r % 30;
    float a;
    if (j < 22)      a = ff[f * 22 + j];
    else if (j < 43) a = fh[h * 21 + (j - 22)];
    else             a = fw[w * 21 + (j - 43)];
    g_cos[idx] = cosf(a);
    g_sin[idx] = sinf(a);
}

// ---------------- split fp32 -> bf16 hi/lo ----------------
__global__ __launch_bounds__(256) void split_kernel(const float* __restrict__ x,
                                                    __nv_bfloat16* __restrict__ hi,
                                                    __nv_bfloat16* __restrict__ lo, int n) {
    int i = blockIdx.x * blockDim.x + threadIdx.x;
    if (i * 4 >= n) return;
    float4 v = *(const float4*)&x[i * 4];
    __nv_bfloat16 h0 = __float2bfloat16(v.x), h1 = __float2bfloat16(v.y);
    __nv_bfloat16 h2 = __float2bfloat16(v.z), h3 = __float2bfloat16(v.w);
    __nv_bfloat16 l0 = __float2bfloat16(v.x - __bfloat162float(h0));
    __nv_bfloat16 l1 = __float2bfloat16(v.y - __bfloat162float(h1));
    __nv_bfloat16 l2 = __float2bfloat16(v.z - __bfloat162float(h2));
    __nv_bfloat16 l3 = __float2bfloat16(v.w - __bfloat162float(h3));
    __nv_bfloat162* ph = (__nv_bfloat162*)&hi[i * 4];
    __nv_bfloat162* pl = (__nv_bfloat162*)&lo[i * 4];
    ph[0] = {h0, h1}; ph[1] = {h2, h3};
    pl[0] = {l0, l1}; pl[1] = {l2, l3};
}

// ---------------- transpose W [K,N] -> Wt [N,K] with hi/lo split ----------------
__global__ __launch_bounds__(256) void transpose_split_kernel(const float* __restrict__ W,
                                                              __nv_bfloat16* __restrict__ Th,
                                                              __nv_bfloat16* __restrict__ Tl) {
    __shared__ float t[32][33];
    int tx = threadIdx.x, ty = threadIdx.y;  // 32 x 8
    int x0 = blockIdx.x * 32, y0 = blockIdx.y * 32;
#pragma unroll
    for (int i = 0; i < 32; i += 8)
        t[ty + i][tx] = W[(size_t)(y0 + ty + i) * DIM + x0 + tx];
    __syncthreads();
#pragma unroll
    for (int i = 0; i < 32; i += 8) {
        float v = t[tx][ty + i];
        __nv_bfloat16 h = __float2bfloat16(v);
        __nv_bfloat16 l = __float2bfloat16(v - __bfloat162float(h));
        size_t o = (size_t)(x0 + ty + i) * DIM + y0 + tx;
        Th[o] = h;
        Tl[o] = l;
    }
}

// ---------------- HMMA split-bf16 GEMM (unchanged from R3) ----------------
#define GK       64
#define TILE_B   16384
#define BUF_B    (4 * TILE_B)
#define GSMEM    (1024 + 2 * BUF_B)

__global__ __launch_bounds__(256, 1) void gemm_hmma(const __nv_bfloat16* __restrict__ Ah,
                                                    const __nv_bfloat16* __restrict__ Al,
                                                    const __nv_bfloat16* __restrict__ Bh,
                                                    const __nv_bfloat16* __restrict__ Bl,
                                                    const float* __restrict__ bias,
                                                    float* __restrict__ C) {
    extern __shared__ char dsm[];
    uint32_t raw = smem_u32(dsm);
    uint32_t sbase = (raw + 1023u) & ~1023u;

    int tid = threadIdx.x;
    int wid = tid >> 5, lane = tid & 31;
    int m0 = blockIdx.y * 128;
    int n0 = blockIdx.x * 128;

    const __nv_bfloat16* srcs[4] = {Ah, Al, Bh, Bl};
    const int rbase[4] = {m0, m0, n0, n0};

    auto load_chunk = [&](int c, int buf) {
        uint32_t dst0 = sbase + (uint32_t)buf * BUF_B;
#pragma unroll
        for (int it = 0; it < 16; it++) {
            int idx = it * 256 + tid;
            int tile = idx >> 10;
            int rem = idx & 1023;
            int r = rem >> 3, g = rem & 7;
            const __nv_bfloat16* src = srcs[tile] + (size_t)(rbase[tile] + r) * DIM + c * GK + g * 8;
            uint32_t off = (uint32_t)(r * 128 + g * 16);
            CP_ASYNC16(dst0 + (uint32_t)tile * TILE_B + SWZ128(off), src);
        }
    };

    float Creg[2][8][4];
#pragma unroll
    for (int mt = 0; mt < 2; mt++)
#pragma unroll
        for (int nf = 0; nf < 8; nf++)
#pragma unroll
            for (int j = 0; j < 4; j++) Creg[mt][nf][j] = 0.f;

    int m_base = (wid & 3) * 32;
    int n_base = (wid >> 2) * 64;
    int a_r = m_base + (lane & 7) + ((lane >> 3) & 1) * 8;
    int a_g = (lane >> 4);
    int b_r = n_base + ((lane >> 4) & 1) * 8 + (lane & 7);
    int b_g = (lane >> 3) & 1;

    const int NCH = DIM / GK;
    load_chunk(0, 0); CP_COMMIT();
    load_chunk(1, 1); CP_COMMIT();

    for (int c = 0; c < NCH; c++) {
        if (c == NCH - 1) CP_WAIT0(); else CP_WAIT1();
        __syncthreads();

        int buf = c & 1;
        uint32_t sb = sbase + (uint32_t)buf * BUF_B;
        uint32_t sAh = sb, sAl = sb + TILE_B, sBh = sb + 2 * TILE_B, sBl = sb + 3 * TILE_B;

#pragma unroll
        for (int ks = 0; ks < 4; ks++) {
            uint32_t ah[2][4], al[2][4], bh[16], bl[16];
#pragma unroll
            for (int mt = 0; mt < 2; mt++) {
                uint32_t off = SWZ128((uint32_t)((a_r + mt * 16) * 128 + (a_g + 2 * ks) * 16));
                ldsm4(ah[mt], sAh + off);
                ldsm4(al[mt], sAl + off);
            }
#pragma unroll
            for (int nf2 = 0; nf2 < 4; nf2++) {
                uint32_t off = SWZ128((uint32_t)((b_r + nf2 * 16) * 128 + (b_g + 2 * ks) * 16));
                ldsm4(&bh[nf2 * 4], sBh + off);
                ldsm4(&bl[nf2 * 4], sBl + off);
            }
#pragma unroll
            for (int nf = 0; nf < 8; nf++) {
                const uint32_t* bhf = &bh[nf * 2];
                const uint32_t* blf = &bl[nf * 2];
#pragma unroll
                for (int mt = 0; mt < 2; mt++) {
                    mma16816(Creg[mt][nf], ah[mt], bhf);
                    mma16816(Creg[mt][nf], ah[mt], blf);
                    mma16816(Creg[mt][nf], al[mt], bhf);
                }
            }
        }
        __syncthreads();
        if (c + 2 < NCH) { load_chunk(c + 2, buf); CP_COMMIT(); }
    }

#pragma unroll
    for (int mt = 0; mt < 2; mt++) {
#pragma unroll
        for (int nf = 0; nf < 8; nf++) {
            int r0 = m0 + m_base + mt * 16 + (lane >> 2);
            int col = n0 + n_base + nf * 8 + (lane & 3) * 2;
            float2 bv = *(const float2*)&bias[col];
            float* cc = Creg[mt][nf];
            float2 o0 = {cc[0] + bv.x, cc[1] + bv.y};
            float2 o1 = {cc[2] + bv.x, cc[3] + bv.y};
            *(float2*)&C[(size_t)r0 * DIM + col] = o0;
            *(float2*)&C[(size_t)(r0 + 8) * DIM + col] = o1;
        }
    }
}

// ---------------- RMSNorm + RoPE -> bf16 hi/lo split ----------------
__global__ __launch_bounds__(256) void rmsnorm_rope_split(const float* __restrict__ x,
                                                          const float* __restrict__ g,
                                                          __nv_bfloat16* __restrict__ oh,
                                                          __nv_bfloat16* __restrict__ ol,
                                                          float outscale) {
    int row = blockIdx.x;
    const float* xp = x + (size_t)row * DIM;
    int tid = threadIdx.x;

    float ss = 0.f;
    for (int i = tid; i < DIM; i += 256) {
        float v = xp[i];
        ss += v * v;
    }
    __shared__ float red[8];
#pragma unroll
    for (int m = 16; m; m >>= 1) ss += __shfl_xor_sync(0xffffffffu, ss, m);
    if ((tid & 31) == 0) red[tid >> 5] = ss;
    __syncthreads();
    if (tid < 8) {
        float v = red[tid];
#pragma unroll
        for (int m = 4; m; m >>= 1) v += __shfl_xor_sync(0xffu, v, m);
        if (tid == 0) red[0] = rsqrtf(v * (1.0f / DIM) + 1e-6f);
    }
    __syncthreads();
    float scale = red[0];

    for (int p = tid; p < NH * NPAIR; p += 256) {
        int head = p >> 6, j = p & 63;
        int i0 = head * HD + 2 * j;
        float2 v = *(const float2*)&xp[i0];
        float2 gv = *(const float2*)&g[i0];
        float xr = v.x * scale * gv.x;
        float xi = v.y * scale * gv.y;
        float c = g_cos[row * NPAIR + j];
        float s = g_sin[row * NPAIR + j];
        float yr = (xr * c - xi * s) * outscale;
        float yi = (xr * s + xi * c) * outscale;
        __nv_bfloat16 hr = __float2bfloat16(yr);
        __nv_bfloat16 hi = __float2bfloat16(yi);
        __nv_bfloat16 lr = __float2bfloat16(yr - __bfloat162float(hr));
        __nv_bfloat16 li = __float2bfloat16(yi - __bfloat162float(hi));
        *(__nv_bfloat162*)&oh[(size_t)row * DIM + i0] = {hr, hi};
        *(__nv_bfloat162*)&ol[(size_t)row * DIM + i0] = {lr, li};
    }
}

// ---------------- HMMA flash attention (frame-causal, split-bf16) ----------------
// grid (30, 12): x = 128-row q-block (reversed), y = head. 256 threads = 8 warps.
// warp w owns q rows [q0 + 16w, q0 + 16w + 16). kv tiles of 64, double-buffered.
#define AST    136                    // padded row stride in bf16 (272B)
#define Q_B    (128 * AST * 2)        // 34816 B per Q operand
#define T_B    (64 * AST * 2)         // 17408 B per KV operand tile
#define ATT_SMEM (2 * Q_B + 8 * T_B)  // 208896 B

__global__ __launch_bounds__(256, 1) void attention_hmma(
    const __nv_bfloat16* __restrict__ Qh, const __nv_bfloat16* __restrict__ Ql,
    const __nv_bfloat16* __restrict__ Kh, const __nv_bfloat16* __restrict__ Kl,
    const __nv_bfloat16* __restrict__ Vh, const __nv_bfloat16* __restrict__ Vl,
    __nv_bfloat16* __restrict__ Oh, __nv_bfloat16* __restrict__ Ol) {
    extern __shared__ char dsm[];
    uint32_t sbase = smem_u32(dsm);
    const uint32_t QH_OFF = 0, QL_OFF = Q_B, KV_OFF = 2 * Q_B;

    int tid = threadIdx.x, wid = tid >> 5, lane = tid & 31;
    int qb = (int)gridDim.x - 1 - blockIdx.x;
    int h = blockIdx.y;
    int q0 = qb * 128;

    // ---- load Q (both operands) ----
    {
        const __nv_bfloat16* gq[2] = {Qh, Ql};
#pragma unroll
        for (int op = 0; op < 2; op++) {
            const __nv_bfloat16* src = gq[op] + (size_t)q0 * DIM + h * HD;
            uint32_t dst = sbase + (op ? QL_OFF : QH_OFF);
#pragma unroll
            for (int it = 0; it < 8; it++) {
                int idx = it * 256 + tid;
                int r = idx >> 4, gg = idx & 15;
                CP_ASYNC16(dst + (uint32_t)(r * 272 + gg * 16), src + (size_t)r * DIM + gg * 8);
            }
        }
    }

    const __nv_bfloat16* gkv[4] = {Kh, Kl, Vh, Vl};
    auto load_kv = [&](int t, int buf) {
        int k0 = t * 64;
#pragma unroll
        for (int op = 0; op < 4; op++) {
            const __nv_bfloat16* src = gkv[op] + (size_t)k0 * DIM + h * HD;
            uint32_t dst = sbase + KV_OFF + (uint32_t)(buf * 4 + op) * T_B;
#pragma unroll
            for (int it = 0; it < 4; it++) {
                int idx = it * 256 + tid;
                int r = idx >> 4, gg = idx & 15;
                CP_ASYNC16(dst + (uint32_t)(r * 272 + gg * 16), src + (size_t)r * DIM + gg * 8);
            }
        }
    };

    float O[16][4];
#pragma unroll
    for (int i = 0; i < 16; i++)
#pragma unroll
        for (int j = 0; j < 4; j++) O[i][j] = 0.f;
    float m0 = -1e30f, m1 = -1e30f, l0 = 0.f, l1 = 0.f;

    int r0g = q0 + wid * 16 + (lane >> 2);
    int fr0 = r0g / FRAME, fr1 = (r0g + 8) / FRAME;
    int blkmin_f = q0 / FRAME;
    int fqmax = (q0 + 127) / FRAME;
    int ntile = ((fqmax + 1) * FRAME + 63) >> 6;

    // ldsm address components
    int a_r = wid * 16 + (lane & 7) + ((lane >> 3) & 1) * 8;
    int a_half = lane >> 4;
    int b_r = ((lane >> 4) & 1) * 8 + (lane & 7);
    int b_half = (lane >> 3) & 1;
    int v_r = (lane & 15);
    int v_c = (lane >> 4) * 8;

    load_kv(0, 0); CP_COMMIT();
    load_kv(1, 1); CP_COMMIT();

    for (int t = 0; t < ntile; t++) {
        if (t == ntile - 1) CP_WAIT0(); else CP_WAIT1();
        __syncthreads();

        int buf = t & 1;
        int k0 = t * 64;
        uint32_t bKh = sbase + KV_OFF + (uint32_t)(buf * 4) * T_B;
        uint32_t bKl = bKh + T_B, bVh = bKh + 2 * T_B, bVl = bKh + 3 * T_B;
        uint32_t bQh = sbase + QH_OFF, bQl = sbase + QL_OFF;

        // ---- S = Q K^T (3-term split) ----
        float S[8][4];
#pragma unroll
        for (int i = 0; i < 8; i++)
#pragma unroll
            for (int j = 0; j < 4; j++) S[i][j] = 0.f;

#pragma unroll
        for (int ks = 0; ks < 8; ks++) {
            uint32_t qa[4], ql4[4], kh4[16], kl4[16];
            uint32_t aoff = (uint32_t)(a_r * 272 + (a_half + 2 * ks) * 16);
            ldsm4(qa, bQh + aoff);
            ldsm4(ql4, bQl + aoff);
#pragma unroll
            for (int nb = 0; nb < 4; nb++) {
                uint32_t boff = (uint32_t)((nb * 16 + b_r) * 272 + (b_half + 2 * ks) * 16);
                ldsm4(&kh4[nb * 4], bKh + boff);
                ldsm4(&kl4[nb * 4], bKl + boff);
            }
#pragma unroll
            for (int nf = 0; nf < 8; nf++) {
                mma16816(S[nf], qa, &kh4[nf * 2]);
                mma16816(S[nf], qa, &kl4[nf * 2]);
                mma16816(S[nf], ql4, &kh4[nf * 2]);
            }
        }

        // ---- mask ----
        if ((k0 + 63) / FRAME > blkmin_f) {
#pragma unroll
            for (int nf = 0; nf < 8; nf++) {
                int c = k0 + nf * 8 + 2 * (lane & 3);
                int cf0 = c / FRAME, cf1 = (c + 1) / FRAME;
                if (cf0 > fr0) S[nf][0] = -1e30f;
                if (cf1 > fr0) S[nf][1] = -1e30f;
                if (cf0 > fr1) S[nf][2] = -1e30f;
                if (cf1 > fr1) S[nf][3] = -1e30f;
            }
        }

        // ---- online softmax ----
        float mx0 = -1e30f, mx1 = -1e30f;
#pragma unroll
        for (int nf = 0; nf < 8; nf++) {
            mx0 = fmaxf(mx0, fmaxf(S[nf][0], S[nf][1]));
            mx1 = fmaxf(mx1, fmaxf(S[nf][2], S[nf][3]));
        }
        mx0 = fmaxf(mx0, __shfl_xor_sync(0xffffffffu, mx0, 1));
        mx0 = fmaxf(mx0, __shfl_xor_sync(0xffffffffu, mx0, 2));
        mx1 = fmaxf(mx1, __shfl_xor_sync(0xffffffffu, mx1, 1));
        mx1 = fmaxf(mx1, __shfl_xor_sync(0xffffffffu, mx1, 2));
        float mn0 = fmaxf(m0, mx0), mn1 = fmaxf(m1, mx1);
        float al0 = exp_fast(m0 - mn0), al1 = exp_fast(m1 - mn1);
        m0 = mn0; m1 = mn1;

        uint32_t Ph[4][4], Pl[4][4];
        float ps0 = 0.f, ps1 = 0.f;
#pragma unroll
        for (int j = 0; j < 4; j++) {
            float p00 = exp_fast(S[2 * j][0] - mn0);
            float p01 = exp_fast(S[2 * j][1] - mn0);
            float p02 = exp_fast(S[2 * j][2] - mn1);
            float p03 = exp_fast(S[2 * j][3] - mn1);
            float p10 = exp_fast(S[2 * j + 1][0] - mn0);
            float p11 = exp_fast(S[2 * j + 1][1] - mn0);
            float p12 = exp_fast(S[2 * j + 1][2] - mn1);
            float p13 = exp_fast(S[2 * j + 1][3] - mn1);
            ps0 += (p00 + p01) + (p10 + p11);
            ps1 += (p02 + p03) + (p12 + p13);
            Ph[j][0] = pack_bf16(p00, p01);
            Ph[j][1] = pack_bf16(p02, p03);
            Ph[j][2] = pack_bf16(p10, p11);
            Ph[j][3] = pack_bf16(p12, p13);
            // residuals
            __nv_bfloat162 h0 = *(__nv_bfloat162*)&Ph[j][0];
            __nv_bfloat162 h1 = *(__nv_bfloat162*)&Ph[j][1];
            __nv_bfloat162 h2 = *(__nv_bfloat162*)&Ph[j][2];
            __nv_bfloat162 h3 = *(__nv_bfloat162*)&Ph[j][3];
            Pl[j][0] = pack_bf16(p00 - __bfloat162float(h0.x), p01 - __bfloat162float(h0.y));
            Pl[j][1] = pack_bf16(p02 - __bfloat162float(h1.x), p03 - __bfloat162float(h1.y));
            Pl[j][2] = pack_bf16(p10 - __bfloat162float(h2.x), p11 - __bfloat162float(h2.y));
            Pl[j][3] = pack_bf16(p12 - __bfloat162float(h3.x), p13 - __bfloat162float(h3.y));
        }
        ps0 += __shfl_xor_sync(0xffffffffu, ps0, 1);
        ps0 += __shfl_xor_sync(0xffffffffu, ps0, 2);
        ps1 += __shfl_xor_sync(0xffffffffu, ps1, 1);
        ps1 += __shfl_xor_sync(0xffffffffu, ps1, 2);
        l0 = l0 * al0 + ps0;
        l1 = l1 * al1 + ps1;
#pragma unroll
        for (int i = 0; i < 16; i++) {
            O[i][0] *= al0; O[i][1] *= al0;
            O[i][2] *= al1; O[i][3] *= al1;
        }

        // ---- O += P V (3-term split); V via ldmatrix.trans ----
#pragma unroll
        for (int j = 0; j < 4; j++) {
#pragma unroll
            for (int db = 0; db < 8; db++) {
                uint32_t vh4[4], vl4[4];
                uint32_t voff = (uint32_t)((j * 16 + v_r) * 272 + (db * 16 + v_c) * 2);
                ldsm4t(vh4, bVh + voff);
                ldsm4t(vl4, bVl + voff);
                mma16816(O[2 * db], Ph[j], &vh4[0]);
                mma16816(O[2 * db], Ph[j], &vl4[0]);
                mma16816(O[2 * db], Pl[j], &vh4[0]);
                mma16816(O[2 * db + 1], Ph[j], &vh4[2]);
                mma16816(O[2 * db + 1], Ph[j], &vl4[2]);
                mma16816(O[2 * db + 1], Pl[j], &vh4[2]);
            }
        }

        __syncthreads();
        if (t + 2 < ntile) { load_kv(t + 2, buf); CP_COMMIT(); }
    }

    // ---- epilogue: normalize, split to bf16 hi/lo, store ----
    float inv0 = 1.0f / l0, inv1 = 1.0f / l1;
    int row0 = q0 + wid * 16 + (lane >> 2);
#pragma unroll
    for (int nf = 0; nf < 16; nf++) {
        int col = h * HD + nf * 8 + 2 * (lane & 3);
        float o00 = O[nf][0] * inv0, o01 = O[nf][1] * inv0;
        float o10 = O[nf][2] * inv1, o11 = O[nf][3] * inv1;
        uint32_t h0 = pack_bf16(o00, o01);
        uint32_t h1 = pack_bf16(o10, o11);
        __nv_bfloat162 hh0 = *(__nv_bfloat162*)&h0;
        __nv_bfloat162 hh1 = *(__nv_bfloat162*)&h1;
        uint32_t lo0 = pack_bf16(o00 - __bfloat162float(hh0.x), o01 - __bfloat162float(hh0.y));
        uint32_t lo1 = pack_bf16(o10 - __bfloat162float(hh1.x), o11 - __bfloat162float(hh1.y));
        *(uint32_t*)&Oh[(size_t)row0 * DIM + col] = h0;
        *(uint32_t*)&Ol[(size_t)row0 * DIM + col] = lo0;
        *(uint32_t*)&Oh[(size_t)(row0 + 8) * DIM + col] = h1;
        *(uint32_t*)&Ol[(size_t)(row0 + 8) * DIM + col] = lo1;
    }
}

// ---------------- launch ----------------
extern "C" void kernel_launch(void* const* d_in, const int* in_sizes, int n_in,
                              void* d_out, int out_size) {
    const float* x  = (const float*)d_in[0];
    const float* Wq = (const float*)d_in[1];
    const float* bq = (const float*)d_in[2];
    const float* Wk = (const float*)d_in[3];
    const float* bk = (const float*)d_in[4];
    const float* Wv = (const float*)d_in[5];
    const float* bv = (const float*)d_in[6];
    const float* Wo = (const float*)d_in[7];
    const float* bo = (const float*)d_in[8];
    const float* gq = (const float*)d_in[9];
    const float* gk = (const float*)d_in[10];
    const float* ff = (const float*)d_in[11];
    const float* fh = (const float*)d_in[12];
    const float* fw = (const float*)d_in[13];
    float* out = (float*)d_out;

    float *qp, *kp, *vp;
    __nv_bfloat16 *ah, *al, *bh, *bl, *qh, *ql, *kh, *kl, *vh, *vl;
    cudaGetSymbolAddress((void**)&qp, g_q);
    cudaGetSymbolAddress((void**)&kp, g_k);
    cudaGetSymbolAddress((void**)&vp, g_v);
    cudaGetSymbolAddress((void**)&ah, g_ah);
    cudaGetSymbolAddress((void**)&al, g_al);
    cudaGetSymbolAddress((void**)&bh, g_bh);
    cudaGetSymbolAddress((void**)&bl, g_bl);
    cudaGetSymbolAddress((void**)&qh, g_qh);
    cudaGetSymbolAddress((void**)&ql, g_ql);
    cudaGetSymbolAddress((void**)&kh, g_kh);
    cudaGetSymbolAddress((void**)&kl, g_kl);
    cudaGetSymbolAddress((void**)&vh, g_vh);
    cudaGetSymbolAddress((void**)&vl, g_vl);

    cudaFuncSetAttribute(gemm_hmma,
                         cudaFuncAttributeMaxDynamicSharedMemorySize, GSMEM);
    cudaFuncSetAttribute(attention_hmma,
                         cudaFuncAttributeMaxDynamicSharedMemorySize, ATT_SMEM);

    angles_kernel<<<(L_TOK * NPAIR + 255) / 256, 256>>>(ff, fh, fw);

    const int NELT = L_TOK * DIM;
    split_kernel<<<(NELT / 4 + 255) / 256, 256>>>(x, ah, al, NELT);

    dim3 tgrid(DIM / 32, DIM / 32), tblk(32, 8);
    dim3 ggrid(DIM / 128, L_TOK / 128);

    transpose_split_kernel<<<tgrid, tblk>>>(Wq, bh, bl);
    gemm_hmma<<<ggrid, 256, GSMEM>>>(ah, al, bh, bl, bq, qp);

    transpose_split_kernel<<<tgrid, tblk>>>(Wk, bh, bl);
    gemm_hmma<<<ggrid, 256, GSMEM>>>(ah, al, bh, bl, bk, kp);

    transpose_split_kernel<<<tgrid, tblk>>>(Wv, bh, bl);
    gemm_hmma<<<ggrid, 256, GSMEM>>>(ah, al, bh, bl, bv, vp);

    // q gets the 1/sqrt(HD) attention scale folded in
    rmsnorm_rope_split<<<L_TOK, 256>>>(qp, gq, qh, ql, 0.08838834764831845f);
    rmsnorm_rope_split<<<L_TOK, 256>>>(kp, gk, kh, kl, 1.0f);
    split_kernel<<<(NELT / 4 + 255) / 256, 256>>>(vp, vh, vl, NELT);

    attention_hmma<<<dim3(30, NH), 256, ATT_SMEM>>>(qh, ql, kh, kl, vh, vl, ah, al);

    transpose_split_kernel<<<tgrid, tblk>>>(Wo, bh, bl);
    gemm_hmma<<<ggrid, 256, GSMEM>>>(ah, al, bh, bl, bo, out);
}

// round 5
// speedup vs baseline: 2.8680x; 1.0166x over previous
#include <cuda_runtime.h>
#include <cuda_bf16.h>
#include <math.h>
#include <stdint.h>

#define L_TOK 3840
#define DIM   1536
#define NH    12
#define HD    128
#define FRAME 480
#define NPAIR 64

// ---------------- device scratch (no allocs allowed) ----------------
__device__ float g_q[L_TOK * DIM];
__device__ float g_k[L_TOK * DIM];
__device__ float g_cos[L_TOK * NPAIR];
__device__ float g_sin[L_TOK * NPAIR];
__device__ __nv_bfloat16 g_ah[L_TOK * DIM];      // GEMM A hi (x, later attn out)
__device__ __nv_bfloat16 g_al[L_TOK * DIM];      // GEMM A lo
__device__ __nv_bfloat16 g_wh[4][DIM * DIM];     // W^T hi  [N][K] for q,k,v,o
__device__ __nv_bfloat16 g_wl[4][DIM * DIM];     // W^T lo
__device__ __nv_bfloat16 g_qh[L_TOK * DIM];
__device__ __nv_bfloat16 g_ql[L_TOK * DIM];
__device__ __nv_bfloat16 g_kh[L_TOK * DIM];
__device__ __nv_bfloat16 g_kl[L_TOK * DIM];
__device__ __nv_bfloat16 g_vh[L_TOK * DIM];
__device__ __nv_bfloat16 g_vl[L_TOK * DIM];

// =================== sm_80-era PTX helpers (valid on plain sm_103) ==========
__device__ __forceinline__ uint32_t smem_u32(const void* p) {
    uint32_t a;
    asm("{ .reg .u64 t; cvta.to.shared.u64 t, %1; cvt.u32.u64 %0, t; }" : "=r"(a) : "l"(p));
    return a;
}
#define CP_ASYNC16(dst, src) \
    asm volatile("cp.async.cg.shared.global [%0], [%1], 16;" :: "r"(dst), "l"(src))
#define CP_COMMIT() asm volatile("cp.async.commit_group;" ::: "memory")
#define CP_WAIT1()  asm volatile("cp.async.wait_group 1;" ::: "memory")
#define CP_WAIT0()  asm volatile("cp.async.wait_group 0;" ::: "memory")

__device__ __forceinline__ void ldsm4(uint32_t* r, uint32_t addr) {
    asm volatile("ldmatrix.sync.aligned.m8n8.x4.shared.b16 {%0,%1,%2,%3}, [%4];"
                 : "=r"(r[0]), "=r"(r[1]), "=r"(r[2]), "=r"(r[3]) : "r"(addr));
}
__device__ __forceinline__ void ldsm4t(uint32_t* r, uint32_t addr) {
    asm volatile("ldmatrix.sync.aligned.m8n8.x4.trans.shared.b16 {%0,%1,%2,%3}, [%4];"
                 : "=r"(r[0]), "=r"(r[1]), "=r"(r[2]), "=r"(r[3]) : "r"(addr));
}
__device__ __forceinline__ void mma16816(float* c, const uint32_t* a, const uint32_t* b) {
    asm volatile("mma.sync.aligned.m16n8k16.row.col.f32.bf16.bf16.f32 "
                 "{%0,%1,%2,%3}, {%4,%5,%6,%7}, {%8,%9}, {%0,%1,%2,%3};"
                 : "+f"(c[0]), "+f"(c[1]), "+f"(c[2]), "+f"(c[3])
                 : "r"(a[0]), "r"(a[1]), "r"(a[2]), "r"(a[3]), "r"(b[0]), "r"(b[1]));
}
#define SWZ128(off) ((off) ^ (((off) >> 3) & 0x70))

__device__ __forceinline__ uint32_t pack_bf16(float lo, float hi) {
    uint32_t r;
    asm("cvt.rn.bf16x2.f32 %0, %1, %2;" : "=r"(r) : "f"(hi), "f"(lo));
    return r;
}
// FFMA-only exp (no MUFU): exp(x) for x <= 0
__device__ __forceinline__ float exp_fast(float x) {
    x = fmaxf(x, -80.0f);
    float y = fmaf(x, 1.4426950408889634f, 12582912.0f);
    float n = y - 12582912.0f;
    float f = fmaf(x, 1.4426950408889634f, -n);
    int e = __float_as_int(y) - 0x4B400000;
    float p = 0.0013333558f;
    p = fmaf(p, f, 0.0096181291f);
    p = fmaf(p, f, 0.0555041087f);
    p = fmaf(p, f, 0.2402265069f);
    p = fmaf(p, f, 0.6931471806f);
    p = fmaf(p, f, 1.0f);
    return __int_as_float(__float_as_int(p) + (e << 23));
}

// ---------------- angle table ----------------
__global__ void angles_kernel(const float* __restrict__ ff,
                              const float* __restrict__ fh,
                              const float* __restrict__ fw) {
    int idx = blockIdx.x * blockDim.x + threadIdx.x;
    if (idx >= L_TOK * NPAIR) return;
    int l = idx / NPAIR, j = idx % NPAIR;
    int f = l / FRAME, r = l % FRAME;
    int h = r / 30, w = r % 30;
    float a;
    if (j < 22)      a = ff[f * 22 + j];
    else if (j < 43) a = fh[h * 21 + (j - 22)];
    else             a = fw[w * 21 + (j - 43)];
    g_cos[idx] = cosf(a);
    g_sin[idx] = sinf(a);
}

// ---------------- split fp32 -> bf16 hi/lo ----------------
__global__ __launch_bounds__(256) void split_kernel(const float* __restrict__ x,
                                                    __nv_bfloat16* __restrict__ hi,
                                                    __nv_bfloat16* __restrict__ lo, int n) {
    int i = blockIdx.x * blockDim.x + threadIdx.x;
    if (i * 4 >= n) return;
    float4 v = *(const float4*)&x[i * 4];
    __nv_bfloat16 h0 = __float2bfloat16(v.x), h1 = __float2bfloat16(v.y);
    __nv_bfloat16 h2 = __float2bfloat16(v.z), h3 = __float2bfloat16(v.w);
    __nv_bfloat16 l0 = __float2bfloat16(v.x - __bfloat162float(h0));
    __nv_bfloat16 l1 = __float2bfloat16(v.y - __bfloat162float(h1));
    __nv_bfloat16 l2 = __float2bfloat16(v.z - __bfloat162float(h2));
    __nv_bfloat16 l3 = __float2bfloat16(v.w - __bfloat162float(h3));
    __nv_bfloat162* ph = (__nv_bfloat162*)&hi[i * 4];
    __nv_bfloat162* pl = (__nv_bfloat162*)&lo[i * 4];
    ph[0] = {h0, h1}; ph[1] = {h2, h3};
    pl[0] = {l0, l1}; pl[1] = {l2, l3};
}

// ---------------- transpose W [K,N] -> Wt [N,K] with hi/lo split ----------------
__global__ __launch_bounds__(256) void transpose_split_kernel(const float* __restrict__ W,
                                                              __nv_bfloat16* __restrict__ Th,
                                                              __nv_bfloat16* __restrict__ Tl) {
    __shared__ float t[32][33];
    int tx = threadIdx.x, ty = threadIdx.y;  // 32 x 8
    int x0 = blockIdx.x * 32, y0 = blockIdx.y * 32;
#pragma unroll
    for (int i = 0; i < 32; i += 8)
        t[ty + i][tx] = W[(size_t)(y0 + ty + i) * DIM + x0 + tx];
    __syncthreads();
#pragma unroll
    for (int i = 0; i < 32; i += 8) {
        float v = t[tx][ty + i];
        __nv_bfloat16 h = __float2bfloat16(v);
        __nv_bfloat16 l = __float2bfloat16(v - __bfloat162float(h));
        size_t o = (size_t)(x0 + ty + i) * DIM + y0 + tx;
        Th[o] = h;
        Tl[o] = l;
    }
}

// ---------------- HMMA split-bf16 GEMM ----------------
// C = A @ W + bias. Term-pass reordering: each of the 3 split terms sweeps all
// 16 independent accumulators -> reuse distance 16 (was 1).
// SPLIT_OUT=1 writes bf16 hi/lo pair instead of fp32.
#define GK       64
#define TILE_B   16384
#define BUF_B    (4 * TILE_B)
#define GSMEM    (1024 + 2 * BUF_B)

template <bool SPLIT_OUT>
__global__ __launch_bounds__(256, 1) void gemm_hmma(const __nv_bfloat16* __restrict__ Ah,
                                                    const __nv_bfloat16* __restrict__ Al,
                                                    const __nv_bfloat16* __restrict__ Bh,
                                                    const __nv_bfloat16* __restrict__ Bl,
                                                    const float* __restrict__ bias,
                                                    float* __restrict__ C,
                                                    __nv_bfloat16* __restrict__ Ch,
                                                    __nv_bfloat16* __restrict__ Cl) {
    extern __shared__ char dsm[];
    uint32_t raw = smem_u32(dsm);
    uint32_t sbase = (raw + 1023u) & ~1023u;

    int tid = threadIdx.x;
    int wid = tid >> 5, lane = tid & 31;
    int m0 = blockIdx.y * 128;
    int n0 = blockIdx.x * 128;

    const __nv_bfloat16* srcs[4] = {Ah, Al, Bh, Bl};
    const int rbase[4] = {m0, m0, n0, n0};

    auto load_chunk = [&](int c, int buf) {
        uint32_t dst0 = sbase + (uint32_t)buf * BUF_B;
#pragma unroll
        for (int it = 0; it < 16; it++) {
            int idx = it * 256 + tid;
            int tile = idx >> 10;
            int rem = idx & 1023;
            int r = rem >> 3, g = rem & 7;
            const __nv_bfloat16* src = srcs[tile] + (size_t)(rbase[tile] + r) * DIM + c * GK + g * 8;
            uint32_t off = (uint32_t)(r * 128 + g * 16);
            CP_ASYNC16(dst0 + (uint32_t)tile * TILE_B + SWZ128(off), src);
        }
    };

    float Creg[2][8][4];
#pragma unroll
    for (int mt = 0; mt < 2; mt++)
#pragma unroll
        for (int nf = 0; nf < 8; nf++)
#pragma unroll
            for (int j = 0; j < 4; j++) Creg[mt][nf][j] = 0.f;

    int m_base = (wid & 3) * 32;
    int n_base = (wid >> 2) * 64;
    int a_r = m_base + (lane & 7) + ((lane >> 3) & 1) * 8;
    int a_g = (lane >> 4);
    int b_r = n_base + ((lane >> 4) & 1) * 8 + (lane & 7);
    int b_g = (lane >> 3) & 1;

    const int NCH = DIM / GK;
    load_chunk(0, 0); CP_COMMIT();
    load_chunk(1, 1); CP_COMMIT();

    for (int c = 0; c < NCH; c++) {
        if (c == NCH - 1) CP_WAIT0(); else CP_WAIT1();
        __syncthreads();

        int buf = c & 1;
        uint32_t sb = sbase + (uint32_t)buf * BUF_B;
        uint32_t sAh = sb, sAl = sb + TILE_B, sBh = sb + 2 * TILE_B, sBl = sb + 3 * TILE_B;

#pragma unroll
        for (int ks = 0; ks < 4; ks++) {
            uint32_t ah[2][4], al[2][4], bh[16], bl[16];
#pragma unroll
            for (int mt = 0; mt < 2; mt++) {
                uint32_t off = SWZ128((uint32_t)((a_r + mt * 16) * 128 + (a_g + 2 * ks) * 16));
                ldsm4(ah[mt], sAh + off);
                ldsm4(al[mt], sAl + off);
            }
#pragma unroll
            for (int nf2 = 0; nf2 < 4; nf2++) {
                uint32_t off = SWZ128((uint32_t)((b_r + nf2 * 16) * 128 + (b_g + 2 * ks) * 16));
                ldsm4(&bh[nf2 * 4], sBh + off);
                ldsm4(&bl[nf2 * 4], sBl + off);
            }
            // term pass 1: Ah * Bh (16 independent accumulators)
#pragma unroll
            for (int nf = 0; nf < 8; nf++)
#pragma unroll
                for (int mt = 0; mt < 2; mt++)
                    mma16816(Creg[mt][nf], ah[mt], &bh[nf * 2]);
            // term pass 2: Ah * Bl
#pragma unroll
            for (int nf = 0; nf < 8; nf++)
#pragma unroll
                for (int mt = 0; mt < 2; mt++)
                    mma16816(Creg[mt][nf], ah[mt], &bl[nf * 2]);
            // term pass 3: Al * Bh
#pragma unroll
            for (int nf = 0; nf < 8; nf++)
#pragma unroll
                for (int mt = 0; mt < 2; mt++)
                    mma16816(Creg[mt][nf], al[mt], &bh[nf * 2]);
        }
        __syncthreads();
        if (c + 2 < NCH) { load_chunk(c + 2, buf); CP_COMMIT(); }
    }

#pragma unroll
    for (int mt = 0; mt < 2; mt++) {
#pragma unroll
        for (int nf = 0; nf < 8; nf++) {
            int r0 = m0 + m_base + mt * 16 + (lane >> 2);
            int col = n0 + n_base + nf * 8 + (lane & 3) * 2;
            float2 bv = *(const float2*)&bias[col];
            float* cc = Creg[mt][nf];
            float c00 = cc[0] + bv.x, c01 = cc[1] + bv.y;
            float c10 = cc[2] + bv.x, c11 = cc[3] + bv.y;
            if (SPLIT_OUT) {
                uint32_t h0 = pack_bf16(c00, c01);
                uint32_t h1 = pack_bf16(c10, c11);
                __nv_bfloat162 hh0 = *(__nv_bfloat162*)&h0;
                __nv_bfloat162 hh1 = *(__nv_bfloat162*)&h1;
                uint32_t lo0 = pack_bf16(c00 - __bfloat162float(hh0.x), c01 - __bfloat162float(hh0.y));
                uint32_t lo1 = pack_bf16(c10 - __bfloat162float(hh1.x), c11 - __bfloat162float(hh1.y));
                *(uint32_t*)&Ch[(size_t)r0 * DIM + col] = h0;
                *(uint32_t*)&Cl[(size_t)r0 * DIM + col] = lo0;
                *(uint32_t*)&Ch[(size_t)(r0 + 8) * DIM + col] = h1;
                *(uint32_t*)&Cl[(size_t)(r0 + 8) * DIM + col] = lo1;
            } else {
                *(float2*)&C[(size_t)r0 * DIM + col] = {c00, c01};
                *(float2*)&C[(size_t)(r0 + 8) * DIM + col] = {c10, c11};
            }
        }
    }
}

// ---------------- RMSNorm + RoPE -> bf16 hi/lo split ----------------
__global__ __launch_bounds__(256) void rmsnorm_rope_split(const float* __restrict__ x,
                                                          const float* __restrict__ g,
                                                          __nv_bfloat16* __restrict__ oh,
                                                          __nv_bfloat16* __restrict__ ol,
                                                          float outscale) {
    int row = blockIdx.x;
    const float* xp = x + (size_t)row * DIM;
    int tid = threadIdx.x;

    float ss = 0.f;
    for (int i = tid; i < DIM; i += 256) {
        float v = xp[i];
        ss += v * v;
    }
    __shared__ float red[8];
#pragma unroll
    for (int m = 16; m; m >>= 1) ss += __shfl_xor_sync(0xffffffffu, ss, m);
    if ((tid & 31) == 0) red[tid >> 5] = ss;
    __syncthreads();
    if (tid < 8) {
        float v = red[tid];
#pragma unroll
        for (int m = 4; m; m >>= 1) v += __shfl_xor_sync(0xffu, v, m);
        if (tid == 0) red[0] = rsqrtf(v * (1.0f / DIM) + 1e-6f);
    }
    __syncthreads();
    float scale = red[0];

    for (int p = tid; p < NH * NPAIR; p += 256) {
        int head = p >> 6, j = p & 63;
        int i0 = head * HD + 2 * j;
        float2 v = *(const float2*)&xp[i0];
        float2 gv = *(const float2*)&g[i0];
        float xr = v.x * scale * gv.x;
        float xi = v.y * scale * gv.y;
        float c = g_cos[row * NPAIR + j];
        float s = g_sin[row * NPAIR + j];
        float yr = (xr * c - xi * s) * outscale;
        float yi = (xr * s + xi * c) * outscale;
        __nv_bfloat16 hr = __float2bfloat16(yr);
        __nv_bfloat16 hi = __float2bfloat16(yi);
        __nv_bfloat16 lr = __float2bfloat16(yr - __bfloat162float(hr));
        __nv_bfloat16 li = __float2bfloat16(yi - __bfloat162float(hi));
        *(__nv_bfloat162*)&oh[(size_t)row * DIM + i0] = {hr, hi};
        *(__nv_bfloat162*)&ol[(size_t)row * DIM + i0] = {lr, li};
    }
}

// ---------------- HMMA flash attention (frame-causal, split-bf16) ----------------
#define AST    136
#define Q_B    (128 * AST * 2)
#define T_B    (64 * AST * 2)
#define ATT_SMEM (2 * Q_B + 8 * T_B)

__global__ __launch_bounds__(256, 1) void attention_hmma(
    const __nv_bfloat16* __restrict__ Qh, const __nv_bfloat16* __restrict__ Ql,
    const __nv_bfloat16* __restrict__ Kh, const __nv_bfloat16* __restrict__ Kl,
    const __nv_bfloat16* __restrict__ Vh, const __nv_bfloat16* __restrict__ Vl,
    __nv_bfloat16* __restrict__ Oh, __nv_bfloat16* __restrict__ Ol) {
    extern __shared__ char dsm[];
    uint32_t sbase = smem_u32(dsm);
    const uint32_t QH_OFF = 0, QL_OFF = Q_B, KV_OFF = 2 * Q_B;

    int tid = threadIdx.x, wid = tid >> 5, lane = tid & 31;
    int qb = (int)gridDim.x - 1 - blockIdx.x;
    int h = blockIdx.y;
    int q0 = qb * 128;

    {
        const __nv_bfloat16* gq[2] = {Qh, Ql};
#pragma unroll
        for (int op = 0; op < 2; op++) {
            const __nv_bfloat16* src = gq[op] + (size_t)q0 * DIM + h * HD;
            uint32_t dst = sbase + (op ? QL_OFF : QH_OFF);
#pragma unroll
            for (int it = 0; it < 8; it++) {
                int idx = it * 256 + tid;
                int r = idx >> 4, gg = idx & 15;
                CP_ASYNC16(dst + (uint32_t)(r * 272 + gg * 16), src + (size_t)r * DIM + gg * 8);
            }
        }
    }

    const __nv_bfloat16* gkv[4] = {Kh, Kl, Vh, Vl};
    auto load_kv = [&](int t, int buf) {
        int k0 = t * 64;
#pragma unroll
        for (int op = 0; op < 4; op++) {
            const __nv_bfloat16* src = gkv[op] + (size_t)k0 * DIM + h * HD;
            uint32_t dst = sbase + KV_OFF + (uint32_t)(buf * 4 + op) * T_B;
#pragma unroll
            for (int it = 0; it < 4; it++) {
                int idx = it * 256 + tid;
                int r = idx >> 4, gg = idx & 15;
                CP_ASYNC16(dst + (uint32_t)(r * 272 + gg * 16), src + (size_t)r * DIM + gg * 8);
            }
        }
    };

    float O[16][4];
#pragma unroll
    for (int i = 0; i < 16; i++)
#pragma unroll
        for (int j = 0; j < 4; j++) O[i][j] = 0.f;
    float m0 = -1e30f, m1 = -1e30f, l0 = 0.f, l1 = 0.f;

    int r0g = q0 + wid * 16 + (lane >> 2);
    int fr0 = r0g / FRAME, fr1 = (r0g + 8) / FRAME;
    int blkmin_f = q0 / FRAME;
    int fqmax = (q0 + 127) / FRAME;
    int ntile = ((fqmax + 1) * FRAME + 63) >> 6;

    int a_r = wid * 16 + (lane & 7) + ((lane >> 3) & 1) * 8;
    int a_half = lane >> 4;
    int b_r = ((lane >> 4) & 1) * 8 + (lane & 7);
    int b_half = (lane >> 3) & 1;
    int v_r = (lane & 15);
    int v_c = (lane >> 4) * 8;

    load_kv(0, 0); CP_COMMIT();
    load_kv(1, 1); CP_COMMIT();

    for (int t = 0; t < ntile; t++) {
        if (t == ntile - 1) CP_WAIT0(); else CP_WAIT1();
        __syncthreads();

        int buf = t & 1;
        int k0 = t * 64;
        uint32_t bKh = sbase + KV_OFF + (uint32_t)(buf * 4) * T_B;
        uint32_t bKl = bKh + T_B, bVh = bKh + 2 * T_B, bVl = bKh + 3 * T_B;
        uint32_t bQh = sbase + QH_OFF, bQl = sbase + QL_OFF;

        // ---- S = Q K^T (3-term split, term-pass reordered) ----
        float S[8][4];
#pragma unroll
        for (int i = 0; i < 8; i++)
#pragma unroll
            for (int j = 0; j < 4; j++) S[i][j] = 0.f;

#pragma unroll
        for (int ks = 0; ks < 8; ks++) {
            uint32_t qa[4], ql4[4], kh4[16], kl4[16];
            uint32_t aoff = (uint32_t)(a_r * 272 + (a_half + 2 * ks) * 16);
            ldsm4(qa, bQh + aoff);
            ldsm4(ql4, bQl + aoff);
#pragma unroll
            for (int nb = 0; nb < 4; nb++) {
                uint32_t boff = (uint32_t)((nb * 16 + b_r) * 272 + (b_half + 2 * ks) * 16);
                ldsm4(&kh4[nb * 4], bKh + boff);
                ldsm4(&kl4[nb * 4], bKl + boff);
            }
#pragma unroll
            for (int nf = 0; nf < 8; nf++) mma16816(S[nf], qa, &kh4[nf * 2]);
#pragma unroll
            for (int nf = 0; nf < 8; nf++) mma16816(S[nf], qa, &kl4[nf * 2]);
#pragma unroll
            for (int nf = 0; nf < 8; nf++) mma16816(S[nf], ql4, &kh4[nf * 2]);
        }

        // ---- mask ----
        if ((k0 + 63) / FRAME > blkmin_f) {
#pragma unroll
            for (int nf = 0; nf < 8; nf++) {
                int c = k0 + nf * 8 + 2 * (lane & 3);
                int cf0 = c / FRAME, cf1 = (c + 1) / FRAME;
                if (cf0 > fr0) S[nf][0] = -1e30f;
                if (cf1 > fr0) S[nf][1] = -1e30f;
                if (cf0 > fr1) S[nf][2] = -1e30f;
                if (cf1 > fr1) S[nf][3] = -1e30f;
            }
        }

        // ---- online softmax ----
        float mx0 = -1e30f, mx1 = -1e30f;
#pragma unroll
        for (int nf = 0; nf < 8; nf++) {
            mx0 = fmaxf(mx0, fmaxf(S[nf][0], S[nf][1]));
            mx1 = fmaxf(mx1, fmaxf(S[nf][2], S[nf][3]));
        }
        mx0 = fmaxf(mx0, __shfl_xor_sync(0xffffffffu, mx0, 1));
        mx0 = fmaxf(mx0, __shfl_xor_sync(0xffffffffu, mx0, 2));
        mx1 = fmaxf(mx1, __shfl_xor_sync(0xffffffffu, mx1, 1));
        mx1 = fmaxf(mx1, __shfl_xor_sync(0xffffffffu, mx1, 2));
        float mn0 = fmaxf(m0, mx0), mn1 = fmaxf(m1, mx1);
        float al0 = exp_fast(m0 - mn0), al1 = exp_fast(m1 - mn1);
        m0 = mn0; m1 = mn1;

        uint32_t Ph[4][4], Pl[4][4];
        float ps0 = 0.f, ps1 = 0.f;
#pragma unroll
        for (int j = 0; j < 4; j++) {
            float p00 = exp_fast(S[2 * j][0] - mn0);
            float p01 = exp_fast(S[2 * j][1] - mn0);
            float p02 = exp_fast(S[2 * j][2] - mn1);
            float p03 = exp_fast(S[2 * j][3] - mn1);
            float p10 = exp_fast(S[2 * j + 1][0] - mn0);
            float p11 = exp_fast(S[2 * j + 1][1] - mn0);
            float p12 = exp_fast(S[2 * j + 1][2] - mn1);
            float p13 = exp_fast(S[2 * j + 1][3] - mn1);
            ps0 += (p00 + p01) + (p10 + p11);
            ps1 += (p02 + p03) + (p12 + p13);
            Ph[j][0] = pack_bf16(p00, p01);
            Ph[j][1] = pack_bf16(p02, p03);
            Ph[j][2] = pack_bf16(p10, p11);
            Ph[j][3] = pack_bf16(p12, p13);
            __nv_bfloat162 h0 = *(__nv_bfloat162*)&Ph[j][0];
            __nv_bfloat162 h1 = *(__nv_bfloat162*)&Ph[j][1];
            __nv_bfloat162 h2 = *(__nv_bfloat162*)&Ph[j][2];
            __nv_bfloat162 h3 = *(__nv_bfloat162*)&Ph[j][3];
            Pl[j][0] = pack_bf16(p00 - __bfloat162float(h0.x), p01 - __bfloat162float(h0.y));
            Pl[j][1] = pack_bf16(p02 - __bfloat162float(h1.x), p03 - __bfloat162float(h1.y));
            Pl[j][2] = pack_bf16(p10 - __bfloat162float(h2.x), p11 - __bfloat162float(h2.y));
            Pl[j][3] = pack_bf16(p12 - __bfloat162float(h3.x), p13 - __bfloat162float(h3.y));
        }
        ps0 += __shfl_xor_sync(0xffffffffu, ps0, 1);
        ps0 += __shfl_xor_sync(0xffffffffu, ps0, 2);
        ps1 += __shfl_xor_sync(0xffffffffu, ps1, 1);
        ps1 += __shfl_xor_sync(0xffffffffu, ps1, 2);
        l0 = l0 * al0 + ps0;
        l1 = l1 * al1 + ps1;
#pragma unroll
        for (int i = 0; i < 16; i++) {
            O[i][0] *= al0; O[i][1] *= al0;
            O[i][2] *= al1; O[i][3] *= al1;
        }

        // ---- O += P V (3-term split; db-pair structure for 4-way ILP) ----
#pragma unroll
        for (int j = 0; j < 4; j++) {
#pragma unroll
            for (int dp = 0; dp < 4; dp++) {
                uint32_t vh_a[4], vh_b[4], vl_a[4], vl_b[4];
                uint32_t voff0 = (uint32_t)((j * 16 + v_r) * 272 + ((2 * dp) * 16 + v_c) * 2);
                uint32_t voff1 = (uint32_t)((j * 16 + v_r) * 272 + ((2 * dp + 1) * 16 + v_c) * 2);
                ldsm4t(vh_a, bVh + voff0);
                ldsm4t(vh_b, bVh + voff1);
                ldsm4t(vl_a, bVl + voff0);
                ldsm4t(vl_b, bVl + voff1);
                float* o0 = O[4 * dp + 0];
                float* o1 = O[4 * dp + 1];
                float* o2 = O[4 * dp + 2];
                float* o3 = O[4 * dp + 3];
                mma16816(o0, Ph[j], &vh_a[0]);
                mma16816(o1, Ph[j], &vh_a[2]);
                mma16816(o2, Ph[j], &vh_b[0]);
                mma16816(o3, Ph[j], &vh_b[2]);
                mma16816(o0, Ph[j], &vl_a[0]);
                mma16816(o1, Ph[j], &vl_a[2]);
                mma16816(o2, Ph[j], &vl_b[0]);
                mma16816(o3, Ph[j], &vl_b[2]);
                mma16816(o0, Pl[j], &vh_a[0]);
                mma16816(o1, Pl[j], &vh_a[2]);
                mma16816(o2, Pl[j], &vh_b[0]);
                mma16816(o3, Pl[j], &vh_b[2]);
            }
        }

        __syncthreads();
        if (t + 2 < ntile) { load_kv(t + 2, buf); CP_COMMIT(); }
    }

    // ---- epilogue ----
    float inv0 = 1.0f / l0, inv1 = 1.0f / l1;
    int row0 = q0 + wid * 16 + (lane >> 2);
#pragma unroll
    for (int nf = 0; nf < 16; nf++) {
        int col = h * HD + nf * 8 + 2 * (lane & 3);
        float o00 = O[nf][0] * inv0, o01 = O[nf][1] * inv0;
        float o10 = O[nf][2] * inv1, o11 = O[nf][3] * inv1;
        uint32_t h0 = pack_bf16(o00, o01);
        uint32_t h1 = pack_bf16(o10, o11);
        __nv_bfloat162 hh0 = *(__nv_bfloat162*)&h0;
        __nv_bfloat162 hh1 = *(__nv_bfloat162*)&h1;
        uint32_t lo0 = pack_bf16(o00 - __bfloat162float(hh0.x), o01 - __bfloat162float(hh0.y));
        uint32_t lo1 = pack_bf16(o10 - __bfloat162float(hh1.x), o11 - __bfloat162float(hh1.y));
        *(uint32_t*)&Oh[(size_t)row0 * DIM + col] = h0;
        *(uint32_t*)&Ol[(size_t)row0 * DIM + col] = lo0;
        *(uint32_t*)&Oh[(size_t)(row0 + 8) * DIM + col] = h1;
        *(uint32_t*)&Ol[(size_t)(row0 + 8) * DIM + col] = lo1;
    }
}

// ---------------- launch ----------------
extern "C" void kernel_launch(void* const* d_in, const int* in_sizes, int n_in,
                              void* d_out, int out_size) {
    const float* x  = (const float*)d_in[0];
    const float* Wq = (const float*)d_in[1];
    const float* bq = (const float*)d_in[2];
    const float* Wk = (const float*)d_in[3];
    const float* bk = (const float*)d_in[4];
    const float* Wv = (const float*)d_in[5];
    const float* bv = (const float*)d_in[6];
    const float* Wo = (const float*)d_in[7];
    const float* bo = (const float*)d_in[8];
    const float* gq = (const float*)d_in[9];
    const float* gk = (const float*)d_in[10];
    const float* ff = (const float*)d_in[11];
    const float* fh = (const float*)d_in[12];
    const float* fw = (const float*)d_in[13];
    float* out = (float*)d_out;

    float *qp, *kp;
    __nv_bfloat16 *ah, *al, *qh, *ql, *kh, *kl, *vh, *vl;
    __nv_bfloat16 (*wh)[DIM * DIM], (*wl)[DIM * DIM];
    cudaGetSymbolAddress((void**)&qp, g_q);
    cudaGetSymbolAddress((void**)&kp, g_k);
    cudaGetSymbolAddress((void**)&ah, g_ah);
    cudaGetSymbolAddress((void**)&al, g_al);
    cudaGetSymbolAddress((void**)&wh, g_wh);
    cudaGetSymbolAddress((void**)&wl, g_wl);
    cudaGetSymbolAddress((void**)&qh, g_qh);
    cudaGetSymbolAddress((void**)&ql, g_ql);
    cudaGetSymbolAddress((void**)&kh, g_kh);
    cudaGetSymbolAddress((void**)&kl, g_kl);
    cudaGetSymbolAddress((void**)&vh, g_vh);
    cudaGetSymbolAddress((void**)&vl, g_vl);

    cudaFuncSetAttribute(gemm_hmma<false>,
                         cudaFuncAttributeMaxDynamicSharedMemorySize, GSMEM);
    cudaFuncSetAttribute(gemm_hmma<true>,
                         cudaFuncAttributeMaxDynamicSharedMemorySize, GSMEM);
    cudaFuncSetAttribute(attention_hmma,
                         cudaFuncAttributeMaxDynamicSharedMemorySize, ATT_SMEM);

    // prep: angles, input split, all weight transposes upfront
    angles_kernel<<<(L_TOK * NPAIR + 255) / 256, 256>>>(ff, fh, fw);

    const int NELT = L_TOK * DIM;
    split_kernel<<<(NELT / 4 + 255) / 256, 256>>>(x, ah, al, NELT);

    dim3 tgrid(DIM / 32, DIM / 32), tblk(32, 8);
    transpose_split_kernel<<<tgrid, tblk>>>(Wq, wh[0], wl[0]);
    transpose_split_kernel<<<tgrid, tblk>>>(Wk, wh[1], wl[1]);
    transpose_split_kernel<<<tgrid, tblk>>>(Wv, wh[2], wl[2]);
    transpose_split_kernel<<<tgrid, tblk>>>(Wo, wh[3], wl[3]);

    dim3 ggrid(DIM / 128, L_TOK / 128);
    gemm_hmma<false><<<ggrid, 256, GSMEM>>>(ah, al, wh[0], wl[0], bq, qp, nullptr, nullptr);
    gemm_hmma<false><<<ggrid, 256, GSMEM>>>(ah, al, wh[1], wl[1], bk, kp, nullptr, nullptr);
    gemm_hmma<true><<<ggrid, 256, GSMEM>>>(ah, al, wh[2], wl[2], bv, nullptr, vh, vl);

    rmsnorm_rope_split<<<L_TOK, 256>>>(qp, gq, qh, ql, 0.08838834764831845f);
    rmsnorm_rope_split<<<L_TOK, 256>>>(kp, gk, kh, kl, 1.0f);

    attention_hmma<<<dim3(30, NH), 256, ATT_SMEM>>>(qh, ql, kh, kl, vh, vl, ah, al);

    gemm_hmma<false><<<ggrid, 256, GSMEM>>>(ah, al, wh[3], wl[3], bo, out, nullptr, nullptr);
}

// round 6
// speedup vs baseline: 3.0548x; 1.0651x over previous
#include <cuda_runtime.h>
#include <cuda_bf16.h>
#include <math.h>
#include <stdint.h>

#define L_TOK 3840
#define DIM   1536
#define NH    12
#define HD    128
#define FRAME 480
#define NPAIR 64

// ---------------- device scratch (no allocs allowed) ----------------
__device__ float g_q[L_TOK * DIM];
__device__ float g_k[L_TOK * DIM];
__device__ float g_cos[L_TOK * NPAIR];
__device__ float g_sin[L_TOK * NPAIR];
__device__ __nv_bfloat16 g_ah[L_TOK * DIM];      // GEMM A hi (x, later attn out)
__device__ __nv_bfloat16 g_al[L_TOK * DIM];      // GEMM A lo
__device__ __nv_bfloat16 g_wh[4][DIM * DIM];     // W^T hi  [N][K] for q,k,v,o
__device__ __nv_bfloat16 g_wl[4][DIM * DIM];     // W^T lo
__device__ __nv_bfloat16 g_qh[L_TOK * DIM];
__device__ __nv_bfloat16 g_ql[L_TOK * DIM];
__device__ __nv_bfloat16 g_kh[L_TOK * DIM];
__device__ __nv_bfloat16 g_kl[L_TOK * DIM];
__device__ __nv_bfloat16 g_vh[L_TOK * DIM];
__device__ __nv_bfloat16 g_vl[L_TOK * DIM];

// =================== sm_80-era PTX helpers (valid on plain sm_103) ==========
__device__ __forceinline__ uint32_t smem_u32(const void* p) {
    uint32_t a;
    asm("{ .reg .u64 t; cvta.to.shared.u64 t, %1; cvt.u32.u64 %0, t; }" : "=r"(a) : "l"(p));
    return a;
}
#define CP_ASYNC16(dst, src) \
    asm volatile("cp.async.cg.shared.global [%0], [%1], 16;" :: "r"(dst), "l"(src))
#define CP_COMMIT() asm volatile("cp.async.commit_group;" ::: "memory")
#define CP_WAIT1()  asm volatile("cp.async.wait_group 1;" ::: "memory")
#define CP_WAIT0()  asm volatile("cp.async.wait_group 0;" ::: "memory")

__device__ __forceinline__ void ldsm4(uint32_t* r, uint32_t addr) {
    asm volatile("ldmatrix.sync.aligned.m8n8.x4.shared.b16 {%0,%1,%2,%3}, [%4];"
                 : "=r"(r[0]), "=r"(r[1]), "=r"(r[2]), "=r"(r[3]) : "r"(addr));
}
__device__ __forceinline__ void ldsm4t(uint32_t* r, uint32_t addr) {
    asm volatile("ldmatrix.sync.aligned.m8n8.x4.trans.shared.b16 {%0,%1,%2,%3}, [%4];"
                 : "=r"(r[0]), "=r"(r[1]), "=r"(r[2]), "=r"(r[3]) : "r"(addr));
}
__device__ __forceinline__ void mma16816(float* c, const uint32_t* a, const uint32_t* b) {
    asm volatile("mma.sync.aligned.m16n8k16.row.col.f32.bf16.bf16.f32 "
                 "{%0,%1,%2,%3}, {%4,%5,%6,%7}, {%8,%9}, {%0,%1,%2,%3};"
                 : "+f"(c[0]), "+f"(c[1]), "+f"(c[2]), "+f"(c[3])
                 : "r"(a[0]), "r"(a[1]), "r"(a[2]), "r"(a[3]), "r"(b[0]), "r"(b[1]));
}
#define SWZ128(off) ((off) ^ (((off) >> 3) & 0x70))

__device__ __forceinline__ uint32_t pack_bf16(float lo, float hi) {
    uint32_t r;
    asm("cvt.rn.bf16x2.f32 %0, %1, %2;" : "=r"(r) : "f"(hi), "f"(lo));
    return r;
}

// ---------------- angle table ----------------
__global__ void angles_kernel(const float* __restrict__ ff,
                              const float* __restrict__ fh,
                              const float* __restrict__ fw) {
    int idx = blockIdx.x * blockDim.x + threadIdx.x;
    if (idx >= L_TOK * NPAIR) return;
    int l = idx / NPAIR, j = idx % NPAIR;
    int f = l / FRAME, r = l % FRAME;
    int h = r / 30, w = r % 30;
    float a;
    if (j < 22)      a = ff[f * 22 + j];
    else if (j < 43) a = fh[h * 21 + (j - 22)];
    else             a = fw[w * 21 + (j - 43)];
    g_cos[idx] = cosf(a);
    g_sin[idx] = sinf(a);
}

// ---------------- split fp32 -> bf16 hi/lo ----------------
__global__ __launch_bounds__(256) void split_kernel(const float* __restrict__ x,
                                                    __nv_bfloat16* __restrict__ hi,
                                                    __nv_bfloat16* __restrict__ lo, int n) {
    int i = blockIdx.x * blockDim.x + threadIdx.x;
    if (i * 4 >= n) return;
    float4 v = *(const float4*)&x[i * 4];
    __nv_bfloat16 h0 = __float2bfloat16(v.x), h1 = __float2bfloat16(v.y);
    __nv_bfloat16 h2 = __float2bfloat16(v.z), h3 = __float2bfloat16(v.w);
    __nv_bfloat16 l0 = __float2bfloat16(v.x - __bfloat162float(h0));
    __nv_bfloat16 l1 = __float2bfloat16(v.y - __bfloat162float(h1));
    __nv_bfloat16 l2 = __float2bfloat16(v.z - __bfloat162float(h2));
    __nv_bfloat16 l3 = __float2bfloat16(v.w - __bfloat162float(h3));
    __nv_bfloat162* ph = (__nv_bfloat162*)&hi[i * 4];
    __nv_bfloat162* pl = (__nv_bfloat162*)&lo[i * 4];
    ph[0] = {h0, h1}; ph[1] = {h2, h3};
    pl[0] = {l0, l1}; pl[1] = {l2, l3};
}

// ------- fused transpose of 4 weights [K,N] -> [N,K] with hi/lo split -------
__global__ __launch_bounds__(256) void transpose_split4_kernel(
    const float* __restrict__ W0, const float* __restrict__ W1,
    const float* __restrict__ W2, const float* __restrict__ W3,
    __nv_bfloat16* __restrict__ ThBase, __nv_bfloat16* __restrict__ TlBase) {
    __shared__ float t[32][33];
    int z = blockIdx.z;
    const float* W = (z == 0) ? W0 : (z == 1) ? W1 : (z == 2) ? W2 : W3;
    __nv_bfloat16* Th = ThBase + (size_t)z * DIM * DIM;
    __nv_bfloat16* Tl = TlBase + (size_t)z * DIM * DIM;
    int tx = threadIdx.x, ty = threadIdx.y;  // 32 x 8
    int x0 = blockIdx.x * 32, y0 = blockIdx.y * 32;
#pragma unroll
    for (int i = 0; i < 32; i += 8)
        t[ty + i][tx] = W[(size_t)(y0 + ty + i) * DIM + x0 + tx];
    __syncthreads();
#pragma unroll
    for (int i = 0; i < 32; i += 8) {
        float v = t[tx][ty + i];
        __nv_bfloat16 h = __float2bfloat16(v);
        __nv_bfloat16 l = __float2bfloat16(v - __bfloat162float(h));
        size_t o = (size_t)(x0 + ty + i) * DIM + y0 + tx;
        Th[o] = h;
        Tl[o] = l;
    }
}

// ---------------- HMMA split-bf16 GEMM (fused multi-weight) ----------------
// blockIdx.z selects the weight/bias/output. Cf==nullptr -> bf16 hi/lo output.
#define GK       64
#define TILE_B   16384
#define BUF_B    (4 * TILE_B)
#define GSMEM    (1024 + 2 * BUF_B)

struct GemmArgs {
    const __nv_bfloat16 *wh0, *wl0, *wh1, *wl1, *wh2, *wl2;
    const float *b0, *b1, *b2;
    float *o0, *o1;                 // fp32 outputs for z=0,1
    __nv_bfloat16 *ovh, *ovl;       // split output for z=2
};

__global__ __launch_bounds__(256, 1) void gemm_hmma(const __nv_bfloat16* __restrict__ Ah,
                                                    const __nv_bfloat16* __restrict__ Al,
                                                    GemmArgs ga) {
    extern __shared__ char dsm[];
    uint32_t raw = smem_u32(dsm);
    uint32_t sbase = (raw + 1023u) & ~1023u;

    int tid = threadIdx.x;
    int wid = tid >> 5, lane = tid & 31;
    int m0 = blockIdx.y * 128;
    int n0 = blockIdx.x * 128;

    const __nv_bfloat16 *Bh, *Bl;
    const float* bias;
    float* Cf;
    if (blockIdx.z == 0)      { Bh = ga.wh0; Bl = ga.wl0; bias = ga.b0; Cf = ga.o0; }
    else if (blockIdx.z == 1) { Bh = ga.wh1; Bl = ga.wl1; bias = ga.b1; Cf = ga.o1; }
    else                      { Bh = ga.wh2; Bl = ga.wl2; bias = ga.b2; Cf = nullptr; }

    const __nv_bfloat16* srcs[4] = {Ah, Al, Bh, Bl};
    const int rbase[4] = {m0, m0, n0, n0};

    auto load_chunk = [&](int c, int buf) {
        uint32_t dst0 = sbase + (uint32_t)buf * BUF_B;
#pragma unroll
        for (int it = 0; it < 16; it++) {
            int idx = it * 256 + tid;
            int tile = idx >> 10;
            int rem = idx & 1023;
            int r = rem >> 3, g = rem & 7;
            const __nv_bfloat16* src = srcs[tile] + (size_t)(rbase[tile] + r) * DIM + c * GK + g * 8;
            uint32_t off = (uint32_t)(r * 128 + g * 16);
            CP_ASYNC16(dst0 + (uint32_t)tile * TILE_B + SWZ128(off), src);
        }
    };

    float Creg[2][8][4];
#pragma unroll
    for (int mt = 0; mt < 2; mt++)
#pragma unroll
        for (int nf = 0; nf < 8; nf++)
#pragma unroll
            for (int j = 0; j < 4; j++) Creg[mt][nf][j] = 0.f;

    int m_base = (wid & 3) * 32;
    int n_base = (wid >> 2) * 64;
    int a_r = m_base + (lane & 7) + ((lane >> 3) & 1) * 8;
    int a_g = (lane >> 4);
    int b_r = n_base + ((lane >> 4) & 1) * 8 + (lane & 7);
    int b_g = (lane >> 3) & 1;

    const int NCH = DIM / GK;
    load_chunk(0, 0); CP_COMMIT();
    load_chunk(1, 1); CP_COMMIT();

    for (int c = 0; c < NCH; c++) {
        if (c == NCH - 1) CP_WAIT0(); else CP_WAIT1();
        __syncthreads();

        int buf = c & 1;
        uint32_t sb = sbase + (uint32_t)buf * BUF_B;
        uint32_t sAh = sb, sAl = sb + TILE_B, sBh = sb + 2 * TILE_B, sBl = sb + 3 * TILE_B;

#pragma unroll
        for (int ks = 0; ks < 4; ks++) {
            uint32_t ah[2][4], al[2][4], bh[16], bl[16];
#pragma unroll
            for (int mt = 0; mt < 2; mt++) {
                uint32_t off = SWZ128((uint32_t)((a_r + mt * 16) * 128 + (a_g + 2 * ks) * 16));
                ldsm4(ah[mt], sAh + off);
                ldsm4(al[mt], sAl + off);
            }
#pragma unroll
            for (int nf2 = 0; nf2 < 4; nf2++) {
                uint32_t off = SWZ128((uint32_t)((b_r + nf2 * 16) * 128 + (b_g + 2 * ks) * 16));
                ldsm4(&bh[nf2 * 4], sBh + off);
                ldsm4(&bl[nf2 * 4], sBl + off);
            }
#pragma unroll
            for (int nf = 0; nf < 8; nf++)
#pragma unroll
                for (int mt = 0; mt < 2; mt++)
                    mma16816(Creg[mt][nf], ah[mt], &bh[nf * 2]);
#pragma unroll
            for (int nf = 0; nf < 8; nf++)
#pragma unroll
                for (int mt = 0; mt < 2; mt++)
                    mma16816(Creg[mt][nf], ah[mt], &bl[nf * 2]);
#pragma unroll
            for (int nf = 0; nf < 8; nf++)
#pragma unroll
                for (int mt = 0; mt < 2; mt++)
                    mma16816(Creg[mt][nf], al[mt], &bh[nf * 2]);
        }
        __syncthreads();
        if (c + 2 < NCH) { load_chunk(c + 2, buf); CP_COMMIT(); }
    }

#pragma unroll
    for (int mt = 0; mt < 2; mt++) {
#pragma unroll
        for (int nf = 0; nf < 8; nf++) {
            int r0 = m0 + m_base + mt * 16 + (lane >> 2);
            int col = n0 + n_base + nf * 8 + (lane & 3) * 2;
            float2 bv = *(const float2*)&bias[col];
            float* cc = Creg[mt][nf];
            float c00 = cc[0] + bv.x, c01 = cc[1] + bv.y;
            float c10 = cc[2] + bv.x, c11 = cc[3] + bv.y;
            if (Cf == nullptr) {
                uint32_t h0 = pack_bf16(c00, c01);
                uint32_t h1 = pack_bf16(c10, c11);
                __nv_bfloat162 hh0 = *(__nv_bfloat162*)&h0;
                __nv_bfloat162 hh1 = *(__nv_bfloat162*)&h1;
                uint32_t lo0 = pack_bf16(c00 - __bfloat162float(hh0.x), c01 - __bfloat162float(hh0.y));
                uint32_t lo1 = pack_bf16(c10 - __bfloat162float(hh1.x), c11 - __bfloat162float(hh1.y));
                *(uint32_t*)&ga.ovh[(size_t)r0 * DIM + col] = h0;
                *(uint32_t*)&ga.ovl[(size_t)r0 * DIM + col] = lo0;
                *(uint32_t*)&ga.ovh[(size_t)(r0 + 8) * DIM + col] = h1;
                *(uint32_t*)&ga.ovl[(size_t)(r0 + 8) * DIM + col] = lo1;
            } else {
                *(float2*)&Cf[(size_t)r0 * DIM + col] = {c00, c01};
                *(float2*)&Cf[(size_t)(r0 + 8) * DIM + col] = {c10, c11};
            }
        }
    }
}

// ---------------- fused RMSNorm + RoPE -> bf16 hi/lo (q and k) ----------------
__global__ __launch_bounds__(256) void rmsnorm_rope_split2(
    const float* __restrict__ xq, const float* __restrict__ xk,
    const float* __restrict__ gqv, const float* __restrict__ gkv,
    __nv_bfloat16* __restrict__ qh, __nv_bfloat16* __restrict__ ql,
    __nv_bfloat16* __restrict__ kh, __nv_bfloat16* __restrict__ kl) {
    int row = blockIdx.x;
    int which = blockIdx.y;
    const float* xp = (which ? xk : xq) + (size_t)row * DIM;
    const float* g = which ? gkv : gqv;
    __nv_bfloat16* oh = which ? kh : qh;
    __nv_bfloat16* ol = which ? kl : ql;
    float outscale = which ? 1.0f : 0.08838834764831845f;
    int tid = threadIdx.x;

    float ss = 0.f;
    for (int i = tid; i < DIM; i += 256) {
        float v = xp[i];
        ss += v * v;
    }
    __shared__ float red[8];
#pragma unroll
    for (int m = 16; m; m >>= 1) ss += __shfl_xor_sync(0xffffffffu, ss, m);
    if ((tid & 31) == 0) red[tid >> 5] = ss;
    __syncthreads();
    if (tid < 8) {
        float v = red[tid];
#pragma unroll
        for (int m = 4; m; m >>= 1) v += __shfl_xor_sync(0xffu, v, m);
        if (tid == 0) red[0] = rsqrtf(v * (1.0f / DIM) + 1e-6f);
    }
    __syncthreads();
    float scale = red[0];

    for (int p = tid; p < NH * NPAIR; p += 256) {
        int head = p >> 6, j = p & 63;
        int i0 = head * HD + 2 * j;
        float2 v = *(const float2*)&xp[i0];
        float2 gv = *(const float2*)&g[i0];
        float xr = v.x * scale * gv.x;
        float xi = v.y * scale * gv.y;
        float c = g_cos[row * NPAIR + j];
        float s = g_sin[row * NPAIR + j];
        float yr = (xr * c - xi * s) * outscale;
        float yi = (xr * s + xi * c) * outscale;
        __nv_bfloat16 hr = __float2bfloat16(yr);
        __nv_bfloat16 hi = __float2bfloat16(yi);
        __nv_bfloat16 lr = __float2bfloat16(yr - __bfloat162float(hr));
        __nv_bfloat16 li = __float2bfloat16(yi - __bfloat162float(hi));
        *(__nv_bfloat162*)&oh[(size_t)row * DIM + i0] = {hr, hi};
        *(__nv_bfloat162*)&ol[(size_t)row * DIM + i0] = {lr, li};
    }
}

// ---------------- HMMA flash attention (frame-causal, split-bf16) ----------------
#define AST    136
#define Q_B    (128 * AST * 2)
#define T_B    (64 * AST * 2)
#define ATT_SMEM (2 * Q_B + 8 * T_B)

__global__ __launch_bounds__(256, 1) void attention_hmma(
    const __nv_bfloat16* __restrict__ Qh, const __nv_bfloat16* __restrict__ Ql,
    const __nv_bfloat16* __restrict__ Kh, const __nv_bfloat16* __restrict__ Kl,
    const __nv_bfloat16* __restrict__ Vh, const __nv_bfloat16* __restrict__ Vl,
    __nv_bfloat16* __restrict__ Oh, __nv_bfloat16* __restrict__ Ol) {
    extern __shared__ char dsm[];
    uint32_t sbase = smem_u32(dsm);
    const uint32_t QH_OFF = 0, QL_OFF = Q_B, KV_OFF = 2 * Q_B;

    int tid = threadIdx.x, wid = tid >> 5, lane = tid & 31;
    int qb = (int)gridDim.x - 1 - blockIdx.x;
    int h = blockIdx.y;
    int q0 = qb * 128;

    {
        const __nv_bfloat16* gq[2] = {Qh, Ql};
#pragma unroll
        for (int op = 0; op < 2; op++) {
            const __nv_bfloat16* src = gq[op] + (size_t)q0 * DIM + h * HD;
            uint32_t dst = sbase + (op ? QL_OFF : QH_OFF);
#pragma unroll
            for (int it = 0; it < 8; it++) {
                int idx = it * 256 + tid;
                int r = idx >> 4, gg = idx & 15;
                CP_ASYNC16(dst + (uint32_t)(r * 272 + gg * 16), src + (size_t)r * DIM + gg * 8);
            }
        }
    }

    const __nv_bfloat16* gkv[4] = {Kh, Kl, Vh, Vl};
    auto load_kv = [&](int t, int buf) {
        int k0 = t * 64;
#pragma unroll
        for (int op = 0; op < 4; op++) {
            const __nv_bfloat16* src = gkv[op] + (size_t)k0 * DIM + h * HD;
            uint32_t dst = sbase + KV_OFF + (uint32_t)(buf * 4 + op) * T_B;
#pragma unroll
            for (int it = 0; it < 4; it++) {
                int idx = it * 256 + tid;
                int r = idx >> 4, gg = idx & 15;
                CP_ASYNC16(dst + (uint32_t)(r * 272 + gg * 16), src + (size_t)r * DIM + gg * 8);
            }
        }
    };

    float O[16][4];
#pragma unroll
    for (int i = 0; i < 16; i++)
#pragma unroll
        for (int j = 0; j < 4; j++) O[i][j] = 0.f;
    float m0 = -1e30f, m1 = -1e30f, l0 = 0.f, l1 = 0.f;

    int r0g = q0 + wid * 16 + (lane >> 2);
    int fr0 = r0g / FRAME, fr1 = (r0g + 8) / FRAME;
    int blkmin_f = q0 / FRAME;
    int fqmax = (q0 + 127) / FRAME;
    int ntile = ((fqmax + 1) * FRAME + 63) >> 6;

    int a_r = wid * 16 + (lane & 7) + ((lane >> 3) & 1) * 8;
    int a_half = lane >> 4;
    int b_r = ((lane >> 4) & 1) * 8 + (lane & 7);
    int b_half = (lane >> 3) & 1;
    int v_r = (lane & 15);
    int v_c = (lane >> 4) * 8;

    load_kv(0, 0); CP_COMMIT();
    load_kv(1, 1); CP_COMMIT();

    for (int t = 0; t < ntile; t++) {
        if (t == ntile - 1) CP_WAIT0(); else CP_WAIT1();
        __syncthreads();

        int buf = t & 1;
        int k0 = t * 64;
        uint32_t bKh = sbase + KV_OFF + (uint32_t)(buf * 4) * T_B;
        uint32_t bKl = bKh + T_B, bVh = bKh + 2 * T_B, bVl = bKh + 3 * T_B;
        uint32_t bQh = sbase + QH_OFF, bQl = sbase + QL_OFF;

        // ---- S = Q K^T (3-term split) ----
        float S[8][4];
#pragma unroll
        for (int i = 0; i < 8; i++)
#pragma unroll
            for (int j = 0; j < 4; j++) S[i][j] = 0.f;

#pragma unroll
        for (int ks = 0; ks < 8; ks++) {
            uint32_t qa[4], ql4[4], kh4[16], kl4[16];
            uint32_t aoff = (uint32_t)(a_r * 272 + (a_half + 2 * ks) * 16);
            ldsm4(qa, bQh + aoff);
            ldsm4(ql4, bQl + aoff);
#pragma unroll
            for (int nb = 0; nb < 4; nb++) {
                uint32_t boff = (uint32_t)((nb * 16 + b_r) * 272 + (b_half + 2 * ks) * 16);
                ldsm4(&kh4[nb * 4], bKh + boff);
                ldsm4(&kl4[nb * 4], bKl + boff);
            }
#pragma unroll
            for (int nf = 0; nf < 8; nf++) mma16816(S[nf], qa, &kh4[nf * 2]);
#pragma unroll
            for (int nf = 0; nf < 8; nf++) mma16816(S[nf], qa, &kl4[nf * 2]);
#pragma unroll
            for (int nf = 0; nf < 8; nf++) mma16816(S[nf], ql4, &kh4[nf * 2]);
        }

        // ---- mask ----
        if ((k0 + 63) / FRAME > blkmin_f) {
#pragma unroll
            for (int nf = 0; nf < 8; nf++) {
                int c = k0 + nf * 8 + 2 * (lane & 3);
                int cf0 = c / FRAME, cf1 = (c + 1) / FRAME;
                if (cf0 > fr0) S[nf][0] = -1e30f;
                if (cf1 > fr0) S[nf][1] = -1e30f;
                if (cf0 > fr1) S[nf][2] = -1e30f;
                if (cf1 > fr1) S[nf][3] = -1e30f;
            }
        }

        // ---- online softmax (MUFU exp) ----
        float mx0 = -1e30f, mx1 = -1e30f;
#pragma unroll
        for (int nf = 0; nf < 8; nf++) {
            mx0 = fmaxf(mx0, fmaxf(S[nf][0], S[nf][1]));
            mx1 = fmaxf(mx1, fmaxf(S[nf][2], S[nf][3]));
        }
        mx0 = fmaxf(mx0, __shfl_xor_sync(0xffffffffu, mx0, 1));
        mx0 = fmaxf(mx0, __shfl_xor_sync(0xffffffffu, mx0, 2));
        mx1 = fmaxf(mx1, __shfl_xor_sync(0xffffffffu, mx1, 1));
        mx1 = fmaxf(mx1, __shfl_xor_sync(0xffffffffu, mx1, 2));
        float mn0 = fmaxf(m0, mx0), mn1 = fmaxf(m1, mx1);
        float al0 = __expf(m0 - mn0), al1 = __expf(m1 - mn1);
        m0 = mn0; m1 = mn1;

        uint32_t Ph[4][4], Pl[4][4];
        float ps0 = 0.f, ps1 = 0.f;
#pragma unroll
        for (int j = 0; j < 4; j++) {
            float p00 = __expf(S[2 * j][0] - mn0);
            float p01 = __expf(S[2 * j][1] - mn0);
            float p02 = __expf(S[2 * j][2] - mn1);
            float p03 = __expf(S[2 * j][3] - mn1);
            float p10 = __expf(S[2 * j + 1][0] - mn0);
            float p11 = __expf(S[2 * j + 1][1] - mn0);
            float p12 = __expf(S[2 * j + 1][2] - mn1);
            float p13 = __expf(S[2 * j + 1][3] - mn1);
            ps0 += (p00 + p01) + (p10 + p11);
            ps1 += (p02 + p03) + (p12 + p13);
            Ph[j][0] = pack_bf16(p00, p01);
            Ph[j][1] = pack_bf16(p02, p03);
            Ph[j][2] = pack_bf16(p10, p11);
            Ph[j][3] = pack_bf16(p12, p13);
            __nv_bfloat162 h0 = *(__nv_bfloat162*)&Ph[j][0];
            __nv_bfloat162 h1 = *(__nv_bfloat162*)&Ph[j][1];
            __nv_bfloat162 h2 = *(__nv_bfloat162*)&Ph[j][2];
            __nv_bfloat162 h3 = *(__nv_bfloat162*)&Ph[j][3];
            Pl[j][0] = pack_bf16(p00 - __bfloat162float(h0.x), p01 - __bfloat162float(h0.y));
            Pl[j][1] = pack_bf16(p02 - __bfloat162float(h1.x), p03 - __bfloat162float(h1.y));
            Pl[j][2] = pack_bf16(p10 - __bfloat162float(h2.x), p11 - __bfloat162float(h2.y));
            Pl[j][3] = pack_bf16(p12 - __bfloat162float(h3.x), p13 - __bfloat162float(h3.y));
        }
        ps0 += __shfl_xor_sync(0xffffffffu, ps0, 1);
        ps0 += __shfl_xor_sync(0xffffffffu, ps0, 2);
        ps1 += __shfl_xor_sync(0xffffffffu, ps1, 1);
        ps1 += __shfl_xor_sync(0xffffffffu, ps1, 2);
        l0 = l0 * al0 + ps0;
        l1 = l1 * al1 + ps1;
#pragma unroll
        for (int i = 0; i < 16; i++) {
            O[i][0] *= al0; O[i][1] *= al0;
            O[i][2] *= al1; O[i][3] *= al1;
        }

        // ---- O += P V ----
#pragma unroll
        for (int j = 0; j < 4; j++) {
#pragma unroll
            for (int dp = 0; dp < 4; dp++) {
                uint32_t vh_a[4], vh_b[4], vl_a[4], vl_b[4];
                uint32_t voff0 = (uint32_t)((j * 16 + v_r) * 272 + ((2 * dp) * 16 + v_c) * 2);
                uint32_t voff1 = (uint32_t)((j * 16 + v_r) * 272 + ((2 * dp + 1) * 16 + v_c) * 2);
                ldsm4t(vh_a, bVh + voff0);
                ldsm4t(vh_b, bVh + voff1);
                ldsm4t(vl_a, bVl + voff0);
                ldsm4t(vl_b, bVl + voff1);
                float* o0 = O[4 * dp + 0];
                float* o1 = O[4 * dp + 1];
                float* o2 = O[4 * dp + 2];
                float* o3 = O[4 * dp + 3];
                mma16816(o0, Ph[j], &vh_a[0]);
                mma16816(o1, Ph[j], &vh_a[2]);
                mma16816(o2, Ph[j], &vh_b[0]);
                mma16816(o3, Ph[j], &vh_b[2]);
                mma16816(o0, Ph[j], &vl_a[0]);
                mma16816(o1, Ph[j], &vl_a[2]);
                mma16816(o2, Ph[j], &vl_b[0]);
                mma16816(o3, Ph[j], &vl_b[2]);
                mma16816(o0, Pl[j], &vh_a[0]);
                mma16816(o1, Pl[j], &vh_a[2]);
                mma16816(o2, Pl[j], &vh_b[0]);
                mma16816(o3, Pl[j], &vh_b[2]);
            }
        }

        __syncthreads();
        if (t + 2 < ntile) { load_kv(t + 2, buf); CP_COMMIT(); }
    }

    // ---- epilogue ----
    float inv0 = 1.0f / l0, inv1 = 1.0f / l1;
    int row0 = q0 + wid * 16 + (lane >> 2);
#pragma unroll
    for (int nf = 0; nf < 16; nf++) {
        int col = h * HD + nf * 8 + 2 * (lane & 3);
        float o00 = O[nf][0] * inv0, o01 = O[nf][1] * inv0;
        float o10 = O[nf][2] * inv1, o11 = O[nf][3] * inv1;
        uint32_t h0 = pack_bf16(o00, o01);
        uint32_t h1 = pack_bf16(o10, o11);
        __nv_bfloat162 hh0 = *(__nv_bfloat162*)&h0;
        __nv_bfloat162 hh1 = *(__nv_bfloat162*)&h1;
        uint32_t lo0 = pack_bf16(o00 - __bfloat162float(hh0.x), o01 - __bfloat162float(hh0.y));
        uint32_t lo1 = pack_bf16(o10 - __bfloat162float(hh1.x), o11 - __bfloat162float(hh1.y));
        *(uint32_t*)&Oh[(size_t)row0 * DIM + col] = h0;
        *(uint32_t*)&Ol[(size_t)row0 * DIM + col] = lo0;
        *(uint32_t*)&Oh[(size_t)(row0 + 8) * DIM + col] = h1;
        *(uint32_t*)&Ol[(size_t)(row0 + 8) * DIM + col] = lo1;
    }
}

// ---------------- launch ----------------
extern "C" void kernel_launch(void* const* d_in, const int* in_sizes, int n_in,
                              void* d_out, int out_size) {
    const float* x  = (const float*)d_in[0];
    const float* Wq = (const float*)d_in[1];
    const float* bq = (const float*)d_in[2];
    const float* Wk = (const float*)d_in[3];
    const float* bk = (const float*)d_in[4];
    const float* Wv = (const float*)d_in[5];
    const float* bv = (const float*)d_in[6];
    const float* Wo = (const float*)d_in[7];
    const float* bo = (const float*)d_in[8];
    const float* gq = (const float*)d_in[9];
    const float* gk = (const float*)d_in[10];
    const float* ff = (const float*)d_in[11];
    const float* fh = (const float*)d_in[12];
    const float* fw = (const float*)d_in[13];
    float* out = (float*)d_out;

    float *qp, *kp;
    __nv_bfloat16 *ah, *al, *qh, *ql, *kh, *kl, *vh, *vl, *whb, *wlb;
    cudaGetSymbolAddress((void**)&qp, g_q);
    cudaGetSymbolAddress((void**)&kp, g_k);
    cudaGetSymbolAddress((void**)&ah, g_ah);
    cudaGetSymbolAddress((void**)&al, g_al);
    cudaGetSymbolAddress((void**)&whb, g_wh);
    cudaGetSymbolAddress((void**)&wlb, g_wl);
    cudaGetSymbolAddress((void**)&qh, g_qh);
    cudaGetSymbolAddress((void**)&ql, g_ql);
    cudaGetSymbolAddress((void**)&kh, g_kh);
    cudaGetSymbolAddress((void**)&kl, g_kl);
    cudaGetSymbolAddress((void**)&vh, g_vh);
    cudaGetSymbolAddress((void**)&vl, g_vl);

    cudaFuncSetAttribute(gemm_hmma,
                         cudaFuncAttributeMaxDynamicSharedMemorySize, GSMEM);
    cudaFuncSetAttribute(attention_hmma,
                         cudaFuncAttributeMaxDynamicSharedMemorySize, ATT_SMEM);

    angles_kernel<<<(L_TOK * NPAIR + 255) / 256, 256>>>(ff, fh, fw);

    const int NELT = L_TOK * DIM;
    split_kernel<<<(NELT / 4 + 255) / 256, 256>>>(x, ah, al, NELT);

    transpose_split4_kernel<<<dim3(DIM / 32, DIM / 32, 4), dim3(32, 8)>>>(
        Wq, Wk, Wv, Wo, whb, wlb);

    const size_t WSZ = (size_t)DIM * DIM;
    GemmArgs ga;
    ga.wh0 = whb;           ga.wl0 = wlb;           ga.b0 = bq; ga.o0 = qp;
    ga.wh1 = whb + WSZ;     ga.wl1 = wlb + WSZ;     ga.b1 = bk; ga.o1 = kp;
    ga.wh2 = whb + 2 * WSZ; ga.wl2 = wlb + 2 * WSZ; ga.b2 = bv;
    ga.ovh = vh;            ga.ovl = vl;
    gemm_hmma<<<dim3(DIM / 128, L_TOK / 128, 3), 256, GSMEM>>>(ah, al, ga);

    rmsnorm_rope_split2<<<dim3(L_TOK, 2), 256>>>(qp, kp, gq, gk, qh, ql, kh, kl);

    attention_hmma<<<dim3(30, NH), 256, ATT_SMEM>>>(qh, ql, kh, kl, vh, vl, ah, al);

    GemmArgs go;
    go.wh0 = whb + 3 * WSZ; go.wl0 = wlb + 3 * WSZ; go.b0 = bo; go.o0 = out;
    go.wh1 = go.wh0; go.wl1 = go.wl0; go.b1 = bo; go.o1 = out;
    go.wh2 = go.wh0; go.wl2 = go.wl0; go.b2 = bo;
    go.ovh = vh; go.ovl = vl;
    gemm_hmma<<<dim3(DIM / 128, L_TOK / 128, 1), 256, GSMEM>>>(ah, al, go);
}